// round 1
// baseline (speedup 1.0000x reference)
#include <cuda_runtime.h>
#include <math.h>

#define BB 2
#define KK 256
#define RR 32
#define DD 192
#define NH 6
#define DH 32
#define NTOK 1024   // 32*32 L4 tokens per batch

// ---------------- scratch (device globals; no allocs allowed) ----------------
__device__ float d_ft0[(size_t)BB*NH*128*128*32];  // level0 channels-last
__device__ float d_ft1[(size_t)BB*NH*64*64*32];    // level1
__device__ float d_ft2[(size_t)BB*NH*32*32*32];    // level2
__device__ float d_gpre[(size_t)BB*NTOK*DD];       // g @ W_u[:,192:384]
__device__ float d_hpre[(size_t)BB*KK*DD];         // h @ W_u[:,0:192] + b_u

// ---------------- feature transpose: [B,192,Hl,Wl] -> [B,H,Hl,Wl,32] ---------
__global__ void transpose_kernel(const float* __restrict__ in, float* __restrict__ outp,
                                 int Hl, int Wl)
{
    __shared__ float s[32][33];
    int x0 = blockIdx.x * 32;
    int y  = blockIdx.y;
    int bh = blockIdx.z;              // b*6 + h
    int b  = bh / NH, hh = bh % NH;
    const float* base = in + (((size_t)b*DD + hh*DH) * Hl + y) * Wl;
    #pragma unroll
    for (int ci = threadIdx.y; ci < 32; ci += 8)
        s[ci][threadIdx.x] = base[(size_t)ci * Hl * Wl + x0 + threadIdx.x];
    __syncthreads();
    float* ob = outp + (((size_t)bh * Hl + y) * Wl) * 32;
    #pragma unroll
    for (int xi = threadIdx.y; xi < 32; xi += 8)
        ob[(size_t)(x0 + xi) * 32 + threadIdx.x] = s[threadIdx.x][xi];
}

// ---------------- precompute X[rows,192] @ W[:, colOff:colOff+192]^T ---------
__global__ void pre_kernel(const float* __restrict__ X,
                           const float* __restrict__ W, int colOff,
                           const float* __restrict__ bias,
                           float* __restrict__ outp)
{
    __shared__ float xs[16][192];
    int r0 = blockIdx.x * 16;
    for (int i = threadIdx.x; i < 16*192; i += 192) {
        int t = i / 192, c = i % 192;
        xs[t][c] = X[(size_t)(r0 + t)*192 + c];
    }
    __syncthreads();
    int d = threadIdx.x;   // 0..191
    float acc[16];
    #pragma unroll
    for (int t = 0; t < 16; ++t) acc[t] = 0.f;
    const float* wr = W + (size_t)d*416 + colOff;
    for (int c = 0; c < 192; c += 4) {
        float4 wv = *(const float4*)(wr + c);
        #pragma unroll
        for (int t = 0; t < 16; ++t) {
            float4 xv = *(const float4*)(&xs[t][c]);
            acc[t] += xv.x*wv.x + xv.y*wv.y + xv.z*wv.z + xv.w*wv.w;
        }
    }
    float bb = bias ? bias[d] : 0.f;
    #pragma unroll
    for (int t = 0; t < 16; ++t)
        outp[(size_t)(r0 + t)*192 + d] = acc[t] + bb;
}

// ---------------- bilinear fetch helper --------------------------------------
__device__ __forceinline__ float fetchv(const float* __restrict__ ft, int x, int y,
                                        int Hl, int Wl)
{
    bool valid = ((unsigned)x < (unsigned)Wl) && ((unsigned)y < (unsigned)Hl);
    return valid ? ft[((size_t)y * Wl + x) * 32] : 0.f;
}

__device__ __forceinline__ float sample_level(const float* __restrict__ ft,
                                              int Hl, int Wl,
                                              float afx, float afy,
                                              const float* __restrict__ offp,
                                              const float* __restrict__ wtp)
{
    float acc = 0.f;
    #pragma unroll
    for (int m = 0; m < 4; ++m) {
        float px = afx + offp[2*m];
        float py = afy + offp[2*m + 1];
        float wgt = wtp[m];
        float x0f = floorf(px), y0f = floorf(py);
        float fx = px - x0f, fy = py - y0f;
        int x0 = (int)x0f, y0 = (int)y0f;
        float v00 = fetchv(ft, x0,     y0,     Hl, Wl);
        float v10 = fetchv(ft, x0 + 1, y0,     Hl, Wl);
        float v01 = fetchv(ft, x0,     y0 + 1, Hl, Wl);
        float v11 = fetchv(ft, x0 + 1, y0 + 1, Hl, Wl);
        float wx0 = 1.f - fx, wy0 = 1.f - fy;
        acc += wgt * (v00*wx0*wy0 + v10*fx*wy0 + v01*wx0*fy + v11*fx*fy);
    }
    return acc;
}

// ---------------- main fused kernel: one block per (b,k), 32 rows ------------
__global__ void __launch_bounds__(256, 2)
main_kernel(const int*   __restrict__ top_indices,
            const float* __restrict__ qc,
            const float* __restrict__ w_u_w,
            const float* __restrict__ ln_g,
            const float* __restrict__ ln_b,
            const float* __restrict__ w_delta_w,
            const float* __restrict__ w_delta_b,
            const float* __restrict__ w_a_w,
            const float* __restrict__ w_a_b,
            const float* __restrict__ w_o_w,
            const float* __restrict__ w_o_b,
            const float* __restrict__ e_def,
            float* __restrict__ out)
{
    extern __shared__ float sm[];
    float* u_sh  = sm;             // 32*192 = 6144
    float* hr    = sm + 6144;      // 32*192 = 6144
    float* phi   = sm + 12288;     // 32*32  = 1024
    float* offs  = sm + 13312;     // 32*144 = 4608  (tanh(raw)*sigma, ready)
    float* wts   = sm + 17920;     // 32*72  = 2304  (logits -> softmax weights)
    float* ax_s  = sm + 20224;     // 32
    float* ay_s  = sm + 20256;     // 32
    int*   idx_s = (int*)(sm + 20288); // 32

    int tid  = threadIdx.x;
    int lane = tid & 31;
    int wid  = tid >> 5;
    int bk   = blockIdx.x;         // b*256 + k
    int b    = bk >> 8;

    // ---- anchors ----
    if (tid < 32) {
        int id = top_indices[(size_t)bk * RR + tid];
        idx_s[tid] = id;
        ax_s[tid] = (float)(id & 31) * 32.f + 16.f;
        ay_s[tid] = (float)(id >> 5) * 32.f + 16.f;
    }
    __syncthreads();

    // ---- fourier PE: 32 rows x 8 freqs, 4 values per thread ----
    {
        int r = tid >> 3, j = tid & 7;
        float qx = qc[(size_t)bk*2 + 0];
        float qy = qc[(size_t)bk*2 + 1];
        float dxn = (ax_s[r] - qx) * (1.f/1024.f);
        float dyn_ = (ay_s[r] - qy) * (1.f/1024.f);
        float f = (float)(1 << j);
        float xa = (dxn * f) * 6.283185307179586f;
        float ya = (dyn_ * f) * 6.283185307179586f;
        float sx, cx, sy, cy;
        sincosf(xa, &sx, &cx);
        sincosf(ya, &sy, &cy);
        phi[r*32 + j]      = sx;
        phi[r*32 + 8 + j]  = cx;
        phi[r*32 + 16 + j] = sy;
        phi[r*32 + 24 + j] = cy;
    }
    __syncthreads();

    // ---- phase A: u = LN(GELU(hpre + gpre[idx] + phi@Wphi)); warp owns 4 rows
    {
        const float* hp = d_hpre + (size_t)bk * DD;
        #pragma unroll
        for (int i = 0; i < 4; ++i) {
            int r = wid*4 + i;
            const float* gp = d_gpre + ((size_t)(b*NTOK + idx_s[r])) * DD;
            float v[6];
            float s1 = 0.f, s2 = 0.f;
            #pragma unroll
            for (int j = 0; j < 6; ++j) {
                int dch = lane + 32*j;
                float acc = hp[dch] + gp[dch];
                const float4* wr = (const float4*)(w_u_w + (size_t)dch*416 + 384);
                const float4* ph = (const float4*)(phi + r*32);
                #pragma unroll
                for (int c4 = 0; c4 < 8; ++c4) {
                    float4 wv = wr[c4]; float4 pv = ph[c4];
                    acc += pv.x*wv.x + pv.y*wv.y + pv.z*wv.z + pv.w*wv.w;
                }
                float gel = 0.5f * acc * (1.f + erff(acc * 0.70710678118654752f));
                v[j] = gel; s1 += gel; s2 += gel*gel;
            }
            #pragma unroll
            for (int off = 16; off; off >>= 1) {
                s1 += __shfl_xor_sync(0xffffffffu, s1, off);
                s2 += __shfl_xor_sync(0xffffffffu, s2, off);
            }
            float mu  = s1 * (1.f/192.f);
            float var = s2 * (1.f/192.f) - mu*mu;
            float rs  = rsqrtf(var + 1e-5f);
            #pragma unroll
            for (int j = 0; j < 6; ++j) {
                int dch = lane + 32*j;
                u_sh[r*192 + dch] = (v[j] - mu) * rs * ln_g[dch] + ln_b[dch];
            }
        }
    }
    __syncthreads();

    // ---- phase B: delta + attn logits; thread owns one output column, 32 rows
    if (tid < 216) {
        int o = tid;
        const float4* wr = (o < 144)
            ? (const float4*)(w_delta_w + (size_t)o * 192)
            : (const float4*)(w_a_w + (size_t)(o - 144) * 192);
        float acc[32];
        #pragma unroll
        for (int r = 0; r < 32; ++r) acc[r] = 0.f;
        for (int c4 = 0; c4 < 48; ++c4) {
            float4 wv = wr[c4];
            #pragma unroll
            for (int r = 0; r < 32; ++r) {
                float4 uv = *(const float4*)(u_sh + r*192 + c4*4);
                acc[r] += uv.x*wv.x + uv.y*wv.y + uv.z*wv.z + uv.w*wv.w;
            }
        }
        if (o < 144) {
            float bb = w_delta_b[o];
            int l = (o >> 3) % 3;                 // o/2 = (h*3+l)*4+m
            float sg = (l == 0) ? 4.f : ((l == 1) ? 2.f : 1.f);
            #pragma unroll
            for (int r = 0; r < 32; ++r)
                offs[r*144 + o] = tanhf(acc[r] + bb) * sg;
        } else {
            int oa = o - 144;
            float bb = w_a_b[oa];
            #pragma unroll
            for (int r = 0; r < 32; ++r)
                wts[r*72 + oa] = acc[r] + bb;
        }
    }
    __syncthreads();

    // ---- softmax over L*M=12 per (row, head); 192 threads ----
    if (tid < 192) {
        int r = tid & 31, hh = tid >> 5;
        float* wp = wts + r*72 + hh*12;
        float mx = wp[0];
        #pragma unroll
        for (int t = 1; t < 12; ++t) mx = fmaxf(mx, wp[t]);
        float s = 0.f;
        #pragma unroll
        for (int t = 0; t < 12; ++t) { float e = expf(wp[t] - mx); wp[t] = e; s += e; }
        float inv = 1.f / s;
        #pragma unroll
        for (int t = 0; t < 12; ++t) wp[t] *= inv;
    }
    __syncthreads();

    // ---- phase C: bilinear sampling; warp owns (row, head) units, lane=channel
    for (int u = wid; u < 192; u += 8) {
        int r = u & 31, hh = u >> 5;
        float axr = ax_s[r], ayr = ay_s[r];
        const float* op = offs + r*144 + hh*24;   // (h*3+l)*8 + m*2
        const float* wp = wts + r*72 + hh*12;
        float acc = 0.f;
        {   // level 0: 128x128, stride 8
            const float* ft = d_ft0 + ((size_t)(b*NH + hh) * 128 * 128) * 32 + lane;
            acc += sample_level(ft, 128, 128, axr*0.125f, ayr*0.125f, op + 0, wp + 0);
        }
        {   // level 1: 64x64, stride 16
            const float* ft = d_ft1 + ((size_t)(b*NH + hh) * 64 * 64) * 32 + lane;
            acc += sample_level(ft, 64, 64, axr*0.0625f, ayr*0.0625f, op + 8, wp + 4);
        }
        {   // level 2: 32x32, stride 32
            const float* ft = d_ft2 + ((size_t)(b*NH + hh) * 32 * 32) * 32 + lane;
            acc += sample_level(ft, 32, 32, axr*0.03125f, ayr*0.03125f, op + 16, wp + 8);
        }
        hr[r*192 + hh*32 + lane] = acc;
    }
    __syncthreads();

    // ---- phase D: output projection; thread owns one output column, 32 rows
    if (tid < 192) {
        int d = tid;
        float acc[32];
        #pragma unroll
        for (int r = 0; r < 32; ++r) acc[r] = 0.f;
        const float4* wr = (const float4*)(w_o_w + (size_t)d * 192);
        for (int c4 = 0; c4 < 48; ++c4) {
            float4 wv = wr[c4];
            #pragma unroll
            for (int r = 0; r < 32; ++r) {
                float4 hv = *(const float4*)(hr + r*192 + c4*4);
                acc[r] += hv.x*wv.x + hv.y*wv.y + hv.z*wv.z + hv.w*wv.w;
            }
        }
        float bb = w_o_b[d] + e_def[d];
        #pragma unroll
        for (int r = 0; r < 32; ++r)
            out[((size_t)bk * RR + r) * 192 + d] = acc[r] + bb;
    }
}

// ---------------- launch ------------------------------------------------------
extern "C" void kernel_launch(void* const* d_in, const int* in_sizes, int n_in,
                              void* d_out, int out_size)
{
    const float* h     = (const float*)d_in[0];
    const int*   top   = (const int*)  d_in[1];
    const float* qc    = (const float*)d_in[2];
    const float* g     = (const float*)d_in[3];
    const float* L2p   = (const float*)d_in[4];
    const float* L3p   = (const float*)d_in[5];
    const float* L4p   = (const float*)d_in[6];
    const float* w_u_w = (const float*)d_in[7];
    const float* w_u_b = (const float*)d_in[8];
    const float* ln_g  = (const float*)d_in[9];
    const float* ln_b  = (const float*)d_in[10];
    const float* w_d_w = (const float*)d_in[11];
    const float* w_d_b = (const float*)d_in[12];
    const float* w_a_w = (const float*)d_in[13];
    const float* w_a_b = (const float*)d_in[14];
    const float* w_o_w = (const float*)d_in[15];
    const float* w_o_b = (const float*)d_in[16];
    const float* e_def = (const float*)d_in[17];
    float* out = (float*)d_out;

    float *ft0, *ft1, *ft2, *gpre, *hpre;
    cudaGetSymbolAddress((void**)&ft0,  d_ft0);
    cudaGetSymbolAddress((void**)&ft1,  d_ft1);
    cudaGetSymbolAddress((void**)&ft2,  d_ft2);
    cudaGetSymbolAddress((void**)&gpre, d_gpre);
    cudaGetSymbolAddress((void**)&hpre, d_hpre);

    dim3 tb(32, 8);
    transpose_kernel<<<dim3(4, 128, BB*NH), tb>>>(L2p, ft0, 128, 128);
    transpose_kernel<<<dim3(2, 64,  BB*NH), tb>>>(L3p, ft1, 64, 64);
    transpose_kernel<<<dim3(1, 32,  BB*NH), tb>>>(L4p, ft2, 32, 32);

    pre_kernel<<<BB*NTOK/16, 192>>>(g, w_u_w, 192, nullptr, gpre);
    pre_kernel<<<BB*KK/16,   192>>>(h, w_u_w, 0,   w_u_b,   hpre);

    const int smem_bytes = 20320 * 4;
    cudaFuncSetAttribute(main_kernel, cudaFuncAttributeMaxDynamicSharedMemorySize, smem_bytes);
    main_kernel<<<BB*KK, 256, smem_bytes>>>(top, qc, w_u_w, ln_g, ln_b,
                                            w_d_w, w_d_b, w_a_w, w_a_b,
                                            w_o_w, w_o_b, e_def, out);
}

// round 2
// speedup vs baseline: 1.4197x; 1.4197x over previous
#include <cuda_runtime.h>
#include <cuda_fp16.h>
#include <math.h>

#define BB 2
#define KK 256
#define RR 32
#define DD 192
#define NH 6
#define DH 32
#define NTOK 1024   // 32*32 L4 tokens per batch

// ---------------- scratch (device globals; no allocs allowed) ----------------
__device__ __half d_ft0[(size_t)BB*NH*128*128*32];  // level0 channels-last fp16
__device__ __half d_ft1[(size_t)BB*NH*64*64*32];    // level1
__device__ __half d_ft2[(size_t)BB*NH*32*32*32];    // level2
__device__ float  d_gpre[(size_t)BB*NTOK*DD];       // g @ W_u[:,192:384]
__device__ float  d_hpre[(size_t)BB*KK*DD];         // h @ W_u[:,0:192] + b_u

// ---------------- f32x2 packed-FMA helpers (Blackwell) ------------------------
__device__ __forceinline__ unsigned long long pack2(float x, float y) {
    unsigned long long r;
    asm("mov.b64 %0, {%1, %2};" : "=l"(r) : "f"(x), "f"(y));
    return r;
}
__device__ __forceinline__ void fma2(unsigned long long& d, unsigned long long a,
                                     unsigned long long b) {
    asm("fma.rn.f32x2 %0, %1, %2, %0;" : "+l"(d) : "l"(a), "l"(b));
}
__device__ __forceinline__ float2 unpack2(unsigned long long v) {
    float2 r;
    asm("mov.b64 {%0, %1}, %2;" : "=f"(r.x), "=f"(r.y) : "l"(v));
    return r;
}

// ---------------- feature transpose: [B,192,Hl,Wl] -> [B,H,Hl,Wl,32] fp16 ----
__global__ void transpose_kernel(const float* __restrict__ in, __half* __restrict__ outp,
                                 int Hl, int Wl)
{
    __shared__ float s[32][33];
    int x0 = blockIdx.x * 32;
    int y  = blockIdx.y;
    int bh = blockIdx.z;              // b*6 + h
    int b  = bh / NH, hh = bh % NH;
    const float* base = in + (((size_t)b*DD + hh*DH) * Hl + y) * Wl;
    #pragma unroll
    for (int ci = threadIdx.y; ci < 32; ci += 8)
        s[ci][threadIdx.x] = base[(size_t)ci * Hl * Wl + x0 + threadIdx.x];
    __syncthreads();
    __half* ob = outp + (((size_t)bh * Hl + y) * Wl) * 32;
    #pragma unroll
    for (int xi = threadIdx.y; xi < 32; xi += 8)
        ob[(size_t)(x0 + xi) * 32 + threadIdx.x] = __float2half(s[threadIdx.x][xi]);
}

// ---------------- precompute X[rows,192] @ W[:, colOff:colOff+192]^T ---------
// 4 rows per block for occupancy (640 blocks total across both calls)
__global__ void pre_kernel(const float* __restrict__ X,
                           const float* __restrict__ W, int colOff,
                           const float* __restrict__ bias,
                           float* __restrict__ outp)
{
    __shared__ float xs[4][192];
    int r0 = blockIdx.x * 4;
    int tid = threadIdx.x;            // 0..191
    #pragma unroll
    for (int t = 0; t < 4; ++t)
        xs[t][tid] = X[(size_t)(r0 + t)*192 + tid];
    __syncthreads();
    float acc[4] = {0.f, 0.f, 0.f, 0.f};
    const float4* wr = (const float4*)(W + (size_t)tid*416 + colOff);
    for (int c4 = 0; c4 < 48; ++c4) {
        float4 wv = wr[c4];
        #pragma unroll
        for (int t = 0; t < 4; ++t) {
            float4 xv = *(const float4*)(&xs[t][c4*4]);
            acc[t] += xv.x*wv.x + xv.y*wv.y + xv.z*wv.z + xv.w*wv.w;
        }
    }
    float bb = bias ? bias[tid] : 0.f;
    #pragma unroll
    for (int t = 0; t < 4; ++t)
        outp[(size_t)(r0 + t)*192 + tid] = acc[t] + bb;
}

// ---------------- bilinear fetch (fp16 features, 2 channels per lane) --------
__device__ __forceinline__ float2 fetch2(const __half2* __restrict__ ft, int x, int y,
                                         int Hl, int Wl)
{
    if (((unsigned)x < (unsigned)Wl) && ((unsigned)y < (unsigned)Hl))
        return __half22float2(ft[((size_t)y * Wl + x) * 16]);
    return make_float2(0.f, 0.f);
}

__device__ __forceinline__ void sample_level2(const __half2* __restrict__ ft,
                                              int Hl, int Wl,
                                              float afx, float afy,
                                              const float* __restrict__ offp,
                                              const float* __restrict__ wtp,
                                              float2& acc)
{
    #pragma unroll
    for (int m = 0; m < 4; ++m) {
        float px = afx + offp[2*m];
        float py = afy + offp[2*m + 1];
        float wgt = wtp[m];
        float x0f = floorf(px), y0f = floorf(py);
        float fx = px - x0f, fy = py - y0f;
        int x0 = (int)x0f, y0 = (int)y0f;
        float2 v00 = fetch2(ft, x0,     y0,     Hl, Wl);
        float2 v10 = fetch2(ft, x0 + 1, y0,     Hl, Wl);
        float2 v01 = fetch2(ft, x0,     y0 + 1, Hl, Wl);
        float2 v11 = fetch2(ft, x0 + 1, y0 + 1, Hl, Wl);
        float wx0 = 1.f - fx, wy0 = 1.f - fy;
        float w00 = wgt*wx0*wy0, w10 = wgt*fx*wy0, w01 = wgt*wx0*fy, w11 = wgt*fx*fy;
        acc.x += v00.x*w00 + v10.x*w10 + v01.x*w01 + v11.x*w11;
        acc.y += v00.y*w00 + v10.y*w10 + v01.y*w01 + v11.y*w11;
    }
}

// ---------------- main fused kernel: one block per (b,k), 32 rows ------------
// smem layout (floats):
//   u_t  [192*34]  column-major, pad 34 (8B-aligned pairs)   0    .. 6528   (= ht later)
//   offs [32*144]                                            6528 .. 11136  (phi aliases start)
//   wts  [32*72]                                             11136.. 13440
//   ax/ay/idx [32 each]                                      13440.. 13536
#define SM_UT   0
#define SM_OFFS 6528
#define SM_PHI  6528
#define SM_WTS  11136
#define SM_AX   13440
#define SM_AY   13472
#define SM_IDX  13504
#define SM_TOTF 13536

__global__ void __launch_bounds__(256, 4)
main_kernel(const int*   __restrict__ top_indices,
            const float* __restrict__ qc,
            const float* __restrict__ w_u_w,
            const float* __restrict__ ln_g,
            const float* __restrict__ ln_b,
            const float* __restrict__ w_delta_w,
            const float* __restrict__ w_delta_b,
            const float* __restrict__ w_a_w,
            const float* __restrict__ w_a_b,
            const float* __restrict__ w_o_w,
            const float* __restrict__ w_o_b,
            const float* __restrict__ e_def,
            float* __restrict__ out)
{
    extern __shared__ float sm[];
    float* u_t  = sm + SM_UT;     // [c*34 + r]
    float* offs = sm + SM_OFFS;
    float* phi  = sm + SM_PHI;    // alias of offs (dead before offs written)
    float* wts  = sm + SM_WTS;
    float* ax_s = sm + SM_AX;
    float* ay_s = sm + SM_AY;
    int*   idx_s = (int*)(sm + SM_IDX);

    int tid  = threadIdx.x;
    int lane = tid & 31;
    int wid  = tid >> 5;
    int bk   = blockIdx.x;         // b*256 + k
    int b    = bk >> 8;

    // ---- anchors ----
    if (tid < 32) {
        int id = top_indices[(size_t)bk * RR + tid];
        idx_s[tid] = id;
        ax_s[tid] = (float)(id & 31) * 32.f + 16.f;
        ay_s[tid] = (float)(id >> 5) * 32.f + 16.f;
    }
    __syncthreads();

    // ---- fourier PE: 32 rows x 8 freqs, 4 values per thread ----
    {
        int r = tid >> 3, j = tid & 7;
        float qx = qc[(size_t)bk*2 + 0];
        float qy = qc[(size_t)bk*2 + 1];
        float dxn  = (ax_s[r] - qx) * (1.f/1024.f);
        float dyn_ = (ay_s[r] - qy) * (1.f/1024.f);
        float f = (float)(1 << j);
        float xa = (dxn  * f) * 6.283185307179586f;
        float ya = (dyn_ * f) * 6.283185307179586f;
        float sx, cx, sy, cy;
        sincosf(xa, &sx, &cx);
        sincosf(ya, &sy, &cy);
        phi[r*32 + j]      = sx;
        phi[r*32 + 8 + j]  = cx;
        phi[r*32 + 16 + j] = sy;
        phi[r*32 + 24 + j] = cy;
    }
    __syncthreads();

    // ---- phase A: column-owner; thread owns channel dch=tid, 32 rows --------
    if (tid < 192) {
        float4 wreg[8];
        const float4* wr = (const float4*)(w_u_w + (size_t)tid*416 + 384);
        #pragma unroll
        for (int i = 0; i < 8; ++i) wreg[i] = wr[i];
        float hbase = d_hpre[(size_t)bk*192 + tid];
        #pragma unroll 4
        for (int r = 0; r < 32; ++r) {
            const float* gp = d_gpre + ((size_t)(b*NTOK + idx_s[r])) * 192;
            float acc = hbase + gp[tid];
            const float4* ph = (const float4*)(phi + r*32);
            #pragma unroll
            for (int c4 = 0; c4 < 8; ++c4) {
                float4 pv = ph[c4], wv = wreg[c4];
                acc += pv.x*wv.x + pv.y*wv.y + pv.z*wv.z + pv.w*wv.w;
            }
            float gel = 0.5f * acc * (1.f + erff(acc * 0.70710678118654752f));
            u_t[tid*34 + r] = gel;
        }
    }
    __syncthreads();

    // ---- LayerNorm in place: warp owns 4 rows -------------------------------
    {
        #pragma unroll
        for (int i = 0; i < 4; ++i) {
            int r = wid*4 + i;
            float v[6]; float s1 = 0.f, s2 = 0.f;
            #pragma unroll
            for (int j = 0; j < 6; ++j) {
                v[j] = u_t[(lane + 32*j)*34 + r];
                s1 += v[j]; s2 += v[j]*v[j];
            }
            #pragma unroll
            for (int off = 16; off; off >>= 1) {
                s1 += __shfl_xor_sync(0xffffffffu, s1, off);
                s2 += __shfl_xor_sync(0xffffffffu, s2, off);
            }
            float mu  = s1 * (1.f/192.f);
            float var = s2 * (1.f/192.f) - mu*mu;
            float rs  = rsqrtf(var + 1e-5f);
            #pragma unroll
            for (int j = 0; j < 6; ++j) {
                int c = lane + 32*j;
                u_t[c*34 + r] = (v[j] - mu) * rs * ln_g[c] + ln_b[c];
            }
        }
    }
    __syncthreads();

    // ---- phase B: delta + logits; thread owns one output column, f32x2 rows -
    if (tid < 216) {
        int o = tid;
        const float4* wr4 = (o < 144)
            ? (const float4*)(w_delta_w + (size_t)o * 192)
            : (const float4*)(w_a_w + (size_t)(o - 144) * 192);
        unsigned long long acc[16];
        #pragma unroll
        for (int p = 0; p < 16; ++p) acc[p] = 0ull;
        for (int c4 = 0; c4 < 48; ++c4) {
            float4 wv = wr4[c4];
            #pragma unroll
            for (int cc = 0; cc < 4; ++cc) {
                float wc = (cc == 0) ? wv.x : (cc == 1) ? wv.y : (cc == 2) ? wv.z : wv.w;
                unsigned long long wpk = pack2(wc, wc);
                const unsigned long long* up =
                    (const unsigned long long*)(u_t + (c4*4 + cc)*34);
                #pragma unroll
                for (int p = 0; p < 16; ++p) fma2(acc[p], up[p], wpk);
            }
        }
        if (o < 144) {
            float bb = w_delta_b[o];
            int l = (o >> 3) % 3;
            float sg = (l == 0) ? 4.f : ((l == 1) ? 2.f : 1.f);
            #pragma unroll
            for (int p = 0; p < 16; ++p) {
                float2 v = unpack2(acc[p]);
                offs[(2*p  )*144 + o] = tanhf(v.x + bb) * sg;
                offs[(2*p+1)*144 + o] = tanhf(v.y + bb) * sg;
            }
        } else {
            int oa = o - 144;
            float bb = w_a_b[oa];
            #pragma unroll
            for (int p = 0; p < 16; ++p) {
                float2 v = unpack2(acc[p]);
                wts[(2*p  )*72 + oa] = v.x + bb;
                wts[(2*p+1)*72 + oa] = v.y + bb;
            }
        }
    }
    __syncthreads();

    // ---- softmax over L*M=12 per (row, head) --------------------------------
    if (tid < 192) {
        int r = tid & 31, hh = tid >> 5;
        float* wp = wts + r*72 + hh*12;
        float mx = wp[0];
        #pragma unroll
        for (int t = 1; t < 12; ++t) mx = fmaxf(mx, wp[t]);
        float s = 0.f;
        #pragma unroll
        for (int t = 0; t < 12; ++t) { float e = expf(wp[t] - mx); wp[t] = e; s += e; }
        float inv = 1.f / s;
        #pragma unroll
        for (int t = 0; t < 12; ++t) wp[t] *= inv;
    }
    __syncthreads();

    // ---- phase C: bilinear sampling; half-warp per (row, head), 2 ch/lane ---
    {
        float* ht = u_t;                  // alias; u values dead now
        int sub = lane >> 4;
        int ch  = (lane & 15) << 1;
        for (int uu = wid*2 + sub; uu < 192; uu += 16) {
            int r = uu & 31, hh = uu >> 5;
            float axr = ax_s[r], ayr = ay_s[r];
            const float* op = offs + r*144 + hh*24;
            const float* wp = wts + r*72 + hh*12;
            float2 acc = make_float2(0.f, 0.f);
            {   // level 0: 128x128, stride 8
                const __half2* ft = (const __half2*)d_ft0
                    + ((size_t)(b*NH + hh) * 128 * 128) * 16 + (ch >> 1);
                sample_level2(ft, 128, 128, axr*0.125f, ayr*0.125f, op + 0, wp + 0, acc);
            }
            {   // level 1: 64x64, stride 16
                const __half2* ft = (const __half2*)d_ft1
                    + ((size_t)(b*NH + hh) * 64 * 64) * 16 + (ch >> 1);
                sample_level2(ft, 64, 64, axr*0.0625f, ayr*0.0625f, op + 8, wp + 4, acc);
            }
            {   // level 2: 32x32, stride 32
                const __half2* ft = (const __half2*)d_ft2
                    + ((size_t)(b*NH + hh) * 32 * 32) * 16 + (ch >> 1);
                sample_level2(ft, 32, 32, axr*0.03125f, ayr*0.03125f, op + 16, wp + 8, acc);
            }
            int c = hh*32 + ch;
            ht[c*34 + r]     = acc.x;
            ht[(c+1)*34 + r] = acc.y;
        }
    }
    __syncthreads();

    // ---- phase D: output projection; thread owns one column, f32x2 rows -----
    if (tid < 192) {
        int d = tid;
        const float* ht = u_t;
        const float4* wr4 = (const float4*)(w_o_w + (size_t)d * 192);
        unsigned long long acc[16];
        #pragma unroll
        for (int p = 0; p < 16; ++p) acc[p] = 0ull;
        for (int c4 = 0; c4 < 48; ++c4) {
            float4 wv = wr4[c4];
            #pragma unroll
            for (int cc = 0; cc < 4; ++cc) {
                float wc = (cc == 0) ? wv.x : (cc == 1) ? wv.y : (cc == 2) ? wv.z : wv.w;
                unsigned long long wpk = pack2(wc, wc);
                const unsigned long long* hp =
                    (const unsigned long long*)(ht + (c4*4 + cc)*34);
                #pragma unroll
                for (int p = 0; p < 16; ++p) fma2(acc[p], hp[p], wpk);
            }
        }
        float bb = w_o_b[d] + e_def[d];
        #pragma unroll
        for (int p = 0; p < 16; ++p) {
            float2 v = unpack2(acc[p]);
            out[((size_t)bk * RR + 2*p    ) * 192 + d] = v.x + bb;
            out[((size_t)bk * RR + 2*p + 1) * 192 + d] = v.y + bb;
        }
    }
}

// ---------------- launch ------------------------------------------------------
extern "C" void kernel_launch(void* const* d_in, const int* in_sizes, int n_in,
                              void* d_out, int out_size)
{
    const float* h     = (const float*)d_in[0];
    const int*   top   = (const int*)  d_in[1];
    const float* qc    = (const float*)d_in[2];
    const float* g     = (const float*)d_in[3];
    const float* L2p   = (const float*)d_in[4];
    const float* L3p   = (const float*)d_in[5];
    const float* L4p   = (const float*)d_in[6];
    const float* w_u_w = (const float*)d_in[7];
    const float* w_u_b = (const float*)d_in[8];
    const float* ln_g  = (const float*)d_in[9];
    const float* ln_b  = (const float*)d_in[10];
    const float* w_d_w = (const float*)d_in[11];
    const float* w_d_b = (const float*)d_in[12];
    const float* w_a_w = (const float*)d_in[13];
    const float* w_a_b = (const float*)d_in[14];
    const float* w_o_w = (const float*)d_in[15];
    const float* w_o_b = (const float*)d_in[16];
    const float* e_def = (const float*)d_in[17];
    float* out = (float*)d_out;

    __half *ft0, *ft1, *ft2;
    float *gpre, *hpre;
    cudaGetSymbolAddress((void**)&ft0,  d_ft0);
    cudaGetSymbolAddress((void**)&ft1,  d_ft1);
    cudaGetSymbolAddress((void**)&ft2,  d_ft2);
    cudaGetSymbolAddress((void**)&gpre, d_gpre);
    cudaGetSymbolAddress((void**)&hpre, d_hpre);

    dim3 tb(32, 8);
    transpose_kernel<<<dim3(4, 128, BB*NH), tb>>>(L2p, ft0, 128, 128);
    transpose_kernel<<<dim3(2, 64,  BB*NH), tb>>>(L3p, ft1, 64, 64);
    transpose_kernel<<<dim3(1, 32,  BB*NH), tb>>>(L4p, ft2, 32, 32);

    pre_kernel<<<BB*NTOK/4, 192>>>(g, w_u_w, 192, nullptr, gpre);
    pre_kernel<<<BB*KK/4,   192>>>(h, w_u_w, 0,   w_u_b,   hpre);

    const int smem_bytes = SM_TOTF * 4;
    cudaFuncSetAttribute(main_kernel, cudaFuncAttributeMaxDynamicSharedMemorySize, smem_bytes);
    main_kernel<<<BB*KK, 256, smem_bytes>>>(top, qc, w_u_w, ln_g, ln_b,
                                            w_d_w, w_d_b, w_a_w, w_a_b,
                                            w_o_w, w_o_b, e_def, out);
}

// round 4
// speedup vs baseline: 1.5267x; 1.0753x over previous
#include <cuda_runtime.h>
#include <cuda_fp16.h>
#include <math.h>

#define BB 2
#define KK 256
#define RR 32
#define DD 192
#define NH 6
#define DH 32
#define NTOK 1024   // 32*32 L4 tokens per batch

// ---------------- scratch (device globals; no allocs allowed) ----------------
__device__ __half d_ft0[(size_t)BB*NH*128*128*32];  // level0 channels-last fp16
__device__ __half d_ft1[(size_t)BB*NH*64*64*32];    // level1
__device__ __half d_ft2[(size_t)BB*NH*32*32*32];    // level2
__device__ float  d_gpre[(size_t)BB*NTOK*DD];       // g @ W_u[:,192:384]
__device__ float  d_hpre[(size_t)BB*KK*DD];         // h @ W_u[:,0:192] + b_u
__device__ float  d_wuT [(size_t)416*192];          // W_u^T  [c][d]
__device__ float  d_wdT2[(size_t)96*216*2];         // delta+a weights, (c/2, o, c%2)
__device__ float  d_woT2[(size_t)96*192*2];         // W_o, (c/2, o, c%2)

// ---------------- f32x2 packed-FMA helpers (Blackwell) ------------------------
__device__ __forceinline__ unsigned long long pack2(float x, float y) {
    unsigned long long r;
    asm("mov.b64 %0, {%1, %2};" : "=l"(r) : "f"(x), "f"(y));
    return r;
}
__device__ __forceinline__ void fma2(unsigned long long& d, unsigned long long a,
                                     unsigned long long b) {
    asm("fma.rn.f32x2 %0, %1, %2, %0;" : "+l"(d) : "l"(a), "l"(b));
}
__device__ __forceinline__ float2 unpack2(unsigned long long v) {
    float2 r;
    asm("mov.b64 {%0, %1}, %2;" : "=f"(r.x), "=f"(r.y) : "l"(v));
    return r;
}

// ---------------- weight prep: transposed / interleaved layouts --------------
__global__ void wprep_kernel(const float* __restrict__ wu,
                             const float* __restrict__ wd,
                             const float* __restrict__ wa,
                             const float* __restrict__ wo)
{
    int i0 = blockIdx.x * blockDim.x + threadIdx.x;
    int stride = gridDim.x * blockDim.x;
    for (int i = i0; i < 416*192; i += stride) {
        int c = i / 192, d = i - c*192;
        d_wuT[i] = wu[(size_t)d*416 + c];
    }
    for (int i = i0; i < 96*216*2; i += stride) {
        int c2 = i / 432; int rem = i - c2*432;
        int o = rem >> 1; int ci = rem & 1;
        int c = 2*c2 + ci;
        d_wdT2[i] = (o < 144) ? wd[(size_t)o*192 + c] : wa[(size_t)(o-144)*192 + c];
    }
    for (int i = i0; i < 96*192*2; i += stride) {
        int c2 = i / 384; int rem = i - c2*384;
        int o = rem >> 1; int ci = rem & 1;
        int c = 2*c2 + ci;
        d_woT2[i] = wo[(size_t)o*192 + c];
    }
}

// ---------------- feature transpose: [B,192,Hl,Wl] -> [B,H,Hl,Wl,32] fp16 ----
__global__ void transpose_kernel(const float* __restrict__ in, __half* __restrict__ outp,
                                 int Hl, int Wl)
{
    __shared__ float s[32][33];
    int x0 = blockIdx.x * 32;
    int y  = blockIdx.y;
    int bh = blockIdx.z;              // b*6 + h
    int b  = bh / NH, hh = bh % NH;
    const float* base = in + (((size_t)b*DD + hh*DH) * Hl + y) * Wl;
    #pragma unroll
    for (int ci = threadIdx.y; ci < 32; ci += 8)
        s[ci][threadIdx.x] = base[(size_t)ci * Hl * Wl + x0 + threadIdx.x];
    __syncthreads();
    __half* ob = outp + (((size_t)bh * Hl + y) * Wl) * 32;
    #pragma unroll
    for (int xi = threadIdx.y; xi < 32; xi += 8)
        ob[(size_t)(x0 + xi) * 32 + threadIdx.x] = __float2half(s[threadIdx.x][xi]);
}

// ---------------- precompute X[rows,192] @ WuT[colOff..colOff+192][192] ------
// 32 rows per block; 192 threads: 4 cols x 8 rows per thread
__global__ void __launch_bounds__(192)
pre2_kernel(const float* __restrict__ X, int colOff,
            const float* __restrict__ bias, float* __restrict__ outp)
{
    __shared__ float xs[32*192];      // row-major [r][c]
    int r0 = blockIdx.x * 32;
    int tid = threadIdx.x;
    for (int i = tid; i < 32*192; i += 192)
        xs[i] = X[(size_t)r0*192 + i];
    __syncthreads();
    int rg = tid / 48;                // 0..3 -> rows rg*8..rg*8+7
    int cg = tid - rg*48;             // 0..47, cols cg+48j
    int rr0 = rg * 8;
    float acc[4][8];
    #pragma unroll
    for (int j = 0; j < 4; ++j)
        #pragma unroll
        for (int q = 0; q < 8; ++q) acc[j][q] = 0.f;
    const float* wbase = d_wuT + (size_t)colOff*192 + cg;
    for (int c = 0; c < 192; ++c) {
        float wv[4];
        #pragma unroll
        for (int j = 0; j < 4; ++j) wv[j] = wbase[c*192 + 48*j];
        #pragma unroll
        for (int q = 0; q < 8; ++q) {
            float xv = xs[(rr0 + q)*192 + c];
            #pragma unroll
            for (int j = 0; j < 4; ++j) acc[j][q] += xv * wv[j];
        }
    }
    #pragma unroll
    for (int j = 0; j < 4; ++j) {
        int col = cg + 48*j;
        float bb = bias ? bias[col] : 0.f;
        #pragma unroll
        for (int q = 0; q < 8; ++q)
            outp[(size_t)(r0 + rr0 + q)*192 + col] = acc[j][q] + bb;
    }
}

// ---------------- main fused kernel ------------------------------------------
// smem layout (floats):
#define SM_UT   0          // u_t [c*34 + r], 192*34 = 6528  (reused as ht)
#define SM_OFFS 6528       // offs [32*144] = 4608 (phi aliases start here)
#define SM_PHI  6528
#define SM_WTS  11136      // wts [32*72] = 2304 (aliased as LN partials first)
#define SM_AX   13440
#define SM_AY   13472
#define SM_IDX  13504
#define SM_MU   13536
#define SM_RS   13568
#define SM_TOTF 13600

__global__ void __launch_bounds__(256, 3)
main_kernel(const int*   __restrict__ top_indices,
            const float* __restrict__ qc,
            const float* __restrict__ ln_g,
            const float* __restrict__ ln_b,
            const float* __restrict__ w_delta_b,
            const float* __restrict__ w_a_b,
            const float* __restrict__ w_o_b,
            const float* __restrict__ e_def,
            float* __restrict__ out)
{
    extern __shared__ float sm[];
    float* u_t  = sm + SM_UT;     // [c*34 + r]
    float* offs = sm + SM_OFFS;
    float* phi  = sm + SM_PHI;
    float* wts  = sm + SM_WTS;
    float* ax_s = sm + SM_AX;
    float* ay_s = sm + SM_AY;
    int*   idx_s = (int*)(sm + SM_IDX);
    float* mu_s = sm + SM_MU;
    float* rs_s = sm + SM_RS;

    int tid  = threadIdx.x;
    int lane = tid & 31;
    int wid  = tid >> 5;
    int bk   = blockIdx.x;         // b*256 + k
    int b    = bk >> 8;

    // ---- anchors ----
    if (tid < 32) {
        int id = top_indices[(size_t)bk * RR + tid];
        idx_s[tid] = id;
        ax_s[tid] = (float)(id & 31) * 32.f + 16.f;
        ay_s[tid] = (float)(id >> 5) * 32.f + 16.f;
    }
    __syncthreads();

    // ---- fourier PE ----
    {
        int r = tid >> 3, j = tid & 7;
        float qx = qc[(size_t)bk*2 + 0];
        float qy = qc[(size_t)bk*2 + 1];
        float dxn  = (ax_s[r] - qx) * (1.f/1024.f);
        float dyn_ = (ay_s[r] - qy) * (1.f/1024.f);
        float f = (float)(1 << j);
        float xa = (dxn  * f) * 6.283185307179586f;
        float ya = (dyn_ * f) * 6.283185307179586f;
        float sx, cx, sy, cy;
        sincosf(xa, &sx, &cx);
        sincosf(ya, &sy, &cy);
        phi[r*32 + j]      = sx;
        phi[r*32 + 8 + j]  = cx;
        phi[r*32 + 16 + j] = sy;
        phi[r*32 + 24 + j] = cy;
    }
    __syncthreads();

    // ---- phase A: gelu(hpre + gpre[idx] + phi @ Wphi^T) -> u_t (pre-LN) ----
    if (tid < 192) {
        float wphi[32];
        #pragma unroll
        for (int i = 0; i < 32; ++i)
            wphi[i] = d_wuT[(size_t)(384 + i)*192 + tid];   // coalesced
        float hbase = d_hpre[(size_t)bk*192 + tid];
        #pragma unroll 2
        for (int r = 0; r < 32; ++r) {
            const float* gp = d_gpre + ((size_t)(b*NTOK + idx_s[r])) * 192;
            float acc = hbase + gp[tid];
            const float4* ph = (const float4*)(phi + r*32);
            #pragma unroll
            for (int c4 = 0; c4 < 8; ++c4) {
                float4 pv = ph[c4];
                acc += pv.x*wphi[4*c4] + pv.y*wphi[4*c4+1]
                     + pv.z*wphi[4*c4+2] + pv.w*wphi[4*c4+3];
            }
            float gel = 0.5f * acc * (1.f + erff(acc * 0.70710678118654752f));
            u_t[tid*34 + r] = gel;
        }
    }
    __syncthreads();

    // ---- LN stats: warp wid sums c-segment [wid*24, wid*24+24), lane = row --
    {
        float s1 = 0.f, s2 = 0.f;
        int c0 = wid * 24;
        for (int cc = c0; cc < c0 + 24; ++cc) {
            float v = u_t[cc*34 + lane];   // conflict-free: lanes consecutive
            s1 += v; s2 += v*v;
        }
        wts[wid*32 + lane]       = s1;     // partials alias wts region
        wts[256 + wid*32 + lane] = s2;
    }
    __syncthreads();
    if (tid < 32) {
        float s1 = 0.f, s2 = 0.f;
        #pragma unroll
        for (int w = 0; w < 8; ++w) {
            s1 += wts[w*32 + tid];
            s2 += wts[256 + w*32 + tid];
        }
        float mu  = s1 * (1.f/192.f);
        float var = s2 * (1.f/192.f) - mu*mu;
        mu_s[tid] = mu;
        rs_s[tid] = rsqrtf(var + 1e-5f);
    }
    __syncthreads();

    // ---- LN apply: column owner ----
    if (tid < 192) {
        float gg = ln_g[tid], bb = ln_b[tid];
        #pragma unroll 4
        for (int r = 0; r < 32; ++r) {
            float v = u_t[tid*34 + r];
            u_t[tid*34 + r] = (v - mu_s[r]) * rs_s[r] * gg + bb;
        }
    }
    __syncthreads();

    // ---- phase B: [32x192] @ [192x216]; 4 cols x 8 rows per thread ----------
    if (tid < 216) {
        int rg = tid / 54;
        int cg = tid - rg*54;
        int r0 = rg * 8;
        unsigned long long acc[4][4];
        #pragma unroll
        for (int j = 0; j < 4; ++j)
            #pragma unroll
            for (int p = 0; p < 4; ++p) acc[j][p] = 0ull;
        const float2* wb = (const float2*)d_wdT2 + cg;
        for (int c2 = 0; c2 < 96; ++c2) {
            unsigned long long u0[4], u1[4];
            const float* ub0 = u_t + (2*c2)*34 + r0;
            const float* ub1 = ub0 + 34;
            #pragma unroll
            for (int p = 0; p < 4; ++p) {
                u0[p] = *(const unsigned long long*)(ub0 + 2*p);
                u1[p] = *(const unsigned long long*)(ub1 + 2*p);
            }
            #pragma unroll
            for (int j = 0; j < 4; ++j) {
                float2 wv = wb[c2*216 + 54*j];
                unsigned long long w0 = pack2(wv.x, wv.x);
                unsigned long long w1 = pack2(wv.y, wv.y);
                #pragma unroll
                for (int p = 0; p < 4; ++p) {
                    fma2(acc[j][p], u0[p], w0);
                    fma2(acc[j][p], u1[p], w1);
                }
            }
        }
        #pragma unroll
        for (int j = 0; j < 4; ++j) {
            int o = cg + 54*j;
            if (o < 144) {
                float bb = w_delta_b[o];
                int l = (o >> 3) % 3;
                float sg = (l == 0) ? 4.f : ((l == 1) ? 2.f : 1.f);
                #pragma unroll
                for (int p = 0; p < 4; ++p) {
                    float2 v = unpack2(acc[j][p]);
                    offs[(r0 + 2*p    )*144 + o] = tanhf(v.x + bb) * sg;
                    offs[(r0 + 2*p + 1)*144 + o] = tanhf(v.y + bb) * sg;
                }
            } else {
                int oa = o - 144;
                float bb = w_a_b[oa];
                #pragma unroll
                for (int p = 0; p < 4; ++p) {
                    float2 v = unpack2(acc[j][p]);
                    wts[(r0 + 2*p    )*72 + oa] = v.x + bb;
                    wts[(r0 + 2*p + 1)*72 + oa] = v.y + bb;
                }
            }
        }
    }
    __syncthreads();

    // ---- softmax over L*M=12 per (row, head) --------------------------------
    if (tid < 192) {
        int r = tid & 31, hh = tid >> 5;
        float* wp = wts + r*72 + hh*12;
        float mx = wp[0];
        #pragma unroll
        for (int t = 1; t < 12; ++t) mx = fmaxf(mx, wp[t]);
        float s = 0.f;
        #pragma unroll
        for (int t = 0; t < 12; ++t) { float e = expf(wp[t] - mx); wp[t] = e; s += e; }
        float inv = 1.f / s;
        #pragma unroll
        for (int t = 0; t < 12; ++t) wp[t] *= inv;
    }
    __syncthreads();

    // ---- phase C: bilinear; 4-lane units, 8 fp16 channels per lane ----------
    {
        float* ht = u_t;                  // alias; u values dead now
        int qlane = lane >> 2;            // unit within warp
        int c8i   = lane & 3;             // channel-quarter (8 ch)
        #pragma unroll
        for (int pass = 0; pass < 3; ++pass) {
            int uu = pass*64 + wid*8 + qlane;
            int r = uu & 31, hh = uu >> 5;
            float axr = ax_s[r], ayr = ay_s[r];
            const float* op = offs + r*144 + hh*24;
            const float* wp = wts + r*72 + hh*12;
            float acc[8];
            #pragma unroll
            for (int k = 0; k < 8; ++k) acc[k] = 0.f;
            #pragma unroll
            for (int l = 0; l < 3; ++l) {
                int Hl = 128 >> l, Wl = 128 >> l;
                const uint4* ft4;
                float scl;
                if (l == 0) { ft4 = (const uint4*)d_ft0 + ((size_t)(b*NH+hh)*128*128)*4 + c8i; scl = 0.125f; }
                else if (l == 1) { ft4 = (const uint4*)d_ft1 + ((size_t)(b*NH+hh)*64*64)*4 + c8i; scl = 0.0625f; }
                else { ft4 = (const uint4*)d_ft2 + ((size_t)(b*NH+hh)*32*32)*4 + c8i; scl = 0.03125f; }
                float afx = axr*scl, afy = ayr*scl;
                #pragma unroll
                for (int m = 0; m < 4; ++m) {
                    float px = afx + op[l*8 + 2*m];
                    float py = afy + op[l*8 + 2*m + 1];
                    float wgt = wp[l*4 + m];
                    float x0f = floorf(px), y0f = floorf(py);
                    float fx = px - x0f, fy = py - y0f;
                    int x0 = (int)x0f, y0 = (int)y0f;
                    float wx0 = 1.f - fx, wy0 = 1.f - fy;
                    float cw[4] = { wgt*wx0*wy0, wgt*fx*wy0, wgt*wx0*fy, wgt*fx*fy };
                    #pragma unroll
                    for (int corner = 0; corner < 4; ++corner) {
                        int xx = x0 + (corner & 1);
                        int yy = y0 + (corner >> 1);
                        if (((unsigned)xx < (unsigned)Wl) && ((unsigned)yy < (unsigned)Hl)) {
                            uint4 raw = ft4[((size_t)yy*Wl + xx)*4];
                            const __half2* hp = (const __half2*)&raw;
                            float w = cw[corner];
                            #pragma unroll
                            for (int k = 0; k < 4; ++k) {
                                float2 f2 = __half22float2(hp[k]);
                                acc[2*k]   += w * f2.x;
                                acc[2*k+1] += w * f2.y;
                            }
                        }
                    }
                }
            }
            int cbase = hh*32 + c8i*8;
            #pragma unroll
            for (int k = 0; k < 8; ++k)
                ht[(cbase + k)*34 + r] = acc[k];
        }
    }
    __syncthreads();

    // ---- phase D: [32x192] @ [192x192]; 4 cols x 8 rows per thread ----------
    if (tid < 192) {
        float* ht = u_t;
        int rg = tid / 48;
        int cg = tid - rg*48;
        int r0 = rg * 8;
        unsigned long long acc[4][4];
        #pragma unroll
        for (int j = 0; j < 4; ++j)
            #pragma unroll
            for (int p = 0; p < 4; ++p) acc[j][p] = 0ull;
        const float2* wb = (const float2*)d_woT2 + cg;
        for (int c2 = 0; c2 < 96; ++c2) {
            unsigned long long u0[4], u1[4];
            const float* ub0 = ht + (2*c2)*34 + r0;
            const float* ub1 = ub0 + 34;
            #pragma unroll
            for (int p = 0; p < 4; ++p) {
                u0[p] = *(const unsigned long long*)(ub0 + 2*p);
                u1[p] = *(const unsigned long long*)(ub1 + 2*p);
            }
            #pragma unroll
            for (int j = 0; j < 4; ++j) {
                float2 wv = wb[c2*192 + 48*j];
                unsigned long long w0 = pack2(wv.x, wv.x);
                unsigned long long w1 = pack2(wv.y, wv.y);
                #pragma unroll
                for (int p = 0; p < 4; ++p) {
                    fma2(acc[j][p], u0[p], w0);
                    fma2(acc[j][p], u1[p], w1);
                }
            }
        }
        #pragma unroll
        for (int j = 0; j < 4; ++j) {
            int d = cg + 48*j;
            float bb = w_o_b[d] + e_def[d];
            #pragma unroll
            for (int p = 0; p < 4; ++p) {
                float2 v = unpack2(acc[j][p]);
                out[((size_t)bk*RR + r0 + 2*p    )*192 + d] = v.x + bb;
                out[((size_t)bk*RR + r0 + 2*p + 1)*192 + d] = v.y + bb;
            }
        }
    }
}

// ---------------- launch ------------------------------------------------------
extern "C" void kernel_launch(void* const* d_in, const int* in_sizes, int n_in,
                              void* d_out, int out_size)
{
    const float* h     = (const float*)d_in[0];
    const int*   top   = (const int*)  d_in[1];
    const float* qc    = (const float*)d_in[2];
    const float* g     = (const float*)d_in[3];
    const float* L2p   = (const float*)d_in[4];
    const float* L3p   = (const float*)d_in[5];
    const float* L4p   = (const float*)d_in[6];
    const float* w_u_w = (const float*)d_in[7];
    const float* w_u_b = (const float*)d_in[8];
    const float* ln_g  = (const float*)d_in[9];
    const float* ln_b  = (const float*)d_in[10];
    const float* w_d_w = (const float*)d_in[11];
    const float* w_d_b = (const float*)d_in[12];
    const float* w_a_w = (const float*)d_in[13];
    const float* w_a_b = (const float*)d_in[14];
    const float* w_o_w = (const float*)d_in[15];
    const float* w_o_b = (const float*)d_in[16];
    const float* e_def = (const float*)d_in[17];
    float* out = (float*)d_out;

    __half *ft0, *ft1, *ft2;
    float *gpre, *hpre;
    cudaGetSymbolAddress((void**)&ft0,  d_ft0);
    cudaGetSymbolAddress((void**)&ft1,  d_ft1);
    cudaGetSymbolAddress((void**)&ft2,  d_ft2);
    cudaGetSymbolAddress((void**)&gpre, d_gpre);
    cudaGetSymbolAddress((void**)&hpre, d_hpre);

    wprep_kernel<<<64, 256>>>(w_u_w, w_d_w, w_a_w, w_o_w);

    dim3 tb(32, 8);
    transpose_kernel<<<dim3(4, 128, BB*NH), tb>>>(L2p, ft0, 128, 128);
    transpose_kernel<<<dim3(2, 64,  BB*NH), tb>>>(L3p, ft1, 64, 64);
    transpose_kernel<<<dim3(1, 32,  BB*NH), tb>>>(L4p, ft2, 32, 32);

    pre2_kernel<<<BB*NTOK/32, 192>>>(g, 192, nullptr, gpre);
    pre2_kernel<<<BB*KK/32,   192>>>(h, 0,   w_u_b,   hpre);

    const int smem_bytes = SM_TOTF * 4;
    cudaFuncSetAttribute(main_kernel, cudaFuncAttributeMaxDynamicSharedMemorySize, smem_bytes);
    main_kernel<<<BB*KK, 256, smem_bytes>>>(top, qc, ln_g, ln_b,
                                            w_d_b, w_a_b, w_o_b, e_def, out);
}

// round 5
// speedup vs baseline: 1.6085x; 1.0536x over previous
#include <cuda_runtime.h>
#include <cuda_fp16.h>
#include <math.h>

#define BB 2
#define KK 256
#define RR 32
#define DD 192
#define NH 6
#define DH 32
#define NTOK 1024   // 32*32 L4 tokens per batch

// ---------------- scratch (device globals; no allocs allowed) ----------------
__device__ __half d_ft0[(size_t)BB*NH*128*128*32];  // level0 channels-last fp16
__device__ __half d_ft1[(size_t)BB*NH*64*64*32];    // level1
__device__ __half d_ft2[(size_t)BB*NH*32*32*32];    // level2
__device__ float  d_gpre[(size_t)BB*NTOK*DD];       // g @ W_u[:,192:384]
__device__ float  d_hpre[(size_t)BB*KK*DD];         // h @ W_u[:,0:192] + b_u
__device__ float  d_wuT [(size_t)416*192];          // W_u^T  [c][d]
__device__ float2 d_wdT2[(size_t)96*216];           // delta+a weights, (c/2, o){c%2}
__device__ float2 d_woT2[(size_t)96*192];           // W_o, (c/2, o){c%2}

// ---------------- f32x2 packed-FMA helpers (Blackwell) ------------------------
__device__ __forceinline__ unsigned long long pack2(float x, float y) {
    unsigned long long r;
    asm("mov.b64 %0, {%1, %2};" : "=l"(r) : "f"(x), "f"(y));
    return r;
}
__device__ __forceinline__ void fma2(unsigned long long& d, unsigned long long a,
                                     unsigned long long b) {
    asm("fma.rn.f32x2 %0, %1, %2, %0;" : "+l"(d) : "l"(a), "l"(b));
}
__device__ __forceinline__ float2 unpack2(unsigned long long v) {
    float2 r;
    asm("mov.b64 {%0, %1}, %2;" : "=f"(r.x), "=f"(r.y) : "l"(v));
    return r;
}

// ---------------- weight prep: transposed / interleaved layouts --------------
__global__ void wprep_kernel(const float* __restrict__ wu,
                             const float* __restrict__ wd,
                             const float* __restrict__ wa,
                             const float* __restrict__ wo)
{
    int i0 = blockIdx.x * blockDim.x + threadIdx.x;
    int stride = gridDim.x * blockDim.x;
    for (int i = i0; i < 416*192; i += stride) {
        int c = i / 192, d = i - c*192;
        d_wuT[i] = wu[(size_t)d*416 + c];
    }
    float* wd2 = (float*)d_wdT2;
    for (int i = i0; i < 96*216*2; i += stride) {
        int c2 = i / 432; int rem = i - c2*432;
        int o = rem >> 1; int ci = rem & 1;
        int c = 2*c2 + ci;
        wd2[i] = (o < 144) ? wd[(size_t)o*192 + c] : wa[(size_t)(o-144)*192 + c];
    }
    float* wo2 = (float*)d_woT2;
    for (int i = i0; i < 96*192*2; i += stride) {
        int c2 = i / 384; int rem = i - c2*384;
        int o = rem >> 1; int ci = rem & 1;
        int c = 2*c2 + ci;
        wo2[i] = wo[(size_t)o*192 + c];
    }
}

// ---------------- merged precompute: X @ WuT slice ---------------------------
// blocks 0..63: g (2048 rows, colOff 192, no bias) -> d_gpre
// blocks 64..79: h (512 rows, colOff 0, +bias)     -> d_hpre
__global__ void __launch_bounds__(192)
pre_merged_kernel(const float* __restrict__ g, const float* __restrict__ h,
                  const float* __restrict__ bias)
{
    __shared__ float xs[32*192];      // row-major [r][c]
    int bx = blockIdx.x;
    const float* X; float* outp; int colOff, r0;
    bool useBias;
    if (bx < 64) { X = g; outp = d_gpre; colOff = 192; r0 = bx*32; useBias = false; }
    else         { X = h; outp = d_hpre; colOff = 0;   r0 = (bx-64)*32; useBias = true; }
    int tid = threadIdx.x;
    for (int i = tid; i < 32*192; i += 192)
        xs[i] = X[(size_t)r0*192 + i];
    __syncthreads();
    int rg = tid & 3;                 // adjacent lanes share cg -> LDG dedup
    int cg = tid >> 2;                // 0..47
    int rr0 = rg * 8;
    float acc[4][8];
    #pragma unroll
    for (int j = 0; j < 4; ++j)
        #pragma unroll
        for (int q = 0; q < 8; ++q) acc[j][q] = 0.f;
    const float* wbase = d_wuT + (size_t)colOff*192 + cg;
    for (int c = 0; c < 192; ++c) {
        float wv[4];
        #pragma unroll
        for (int j = 0; j < 4; ++j) wv[j] = wbase[c*192 + 48*j];
        #pragma unroll
        for (int q = 0; q < 8; ++q) {
            float xv = xs[(rr0 + q)*192 + c];
            #pragma unroll
            for (int j = 0; j < 4; ++j) acc[j][q] += xv * wv[j];
        }
    }
    #pragma unroll
    for (int j = 0; j < 4; ++j) {
        int col = cg + 48*j;
        float bb = useBias ? bias[col] : 0.f;
        #pragma unroll
        for (int q = 0; q < 8; ++q)
            outp[(size_t)(r0 + rr0 + q)*192 + col] = acc[j][q] + bb;
    }
}

// ---------------- merged feature transpose -----------------------------------
// flattened grid: level0 6144, level1 1536, level2 384 blocks
__global__ void transpose_merged_kernel(const float* __restrict__ L2p,
                                        const float* __restrict__ L3p,
                                        const float* __restrict__ L4p)
{
    __shared__ float s[32][33];
    int bid = blockIdx.x;
    const float* in; __half* outp; int Hl, Wl, xb, y, bh;
    if (bid < 6144) {
        Hl = Wl = 128; in = L2p; outp = d_ft0;
        int t = bid; xb = t & 3; t >>= 2; y = t & 127; bh = t >> 7;
    } else if (bid < 7680) {
        Hl = Wl = 64; in = L3p; outp = d_ft1;
        int t = bid - 6144; xb = t & 1; t >>= 1; y = t & 63; bh = t >> 6;
    } else {
        Hl = Wl = 32; in = L4p; outp = d_ft2;
        int t = bid - 7680; xb = 0; y = t & 31; bh = t >> 5;
    }
    int x0 = xb * 32;
    int b = bh / NH, hh = bh % NH;
    const float* base = in + (((size_t)b*DD + hh*DH) * Hl + y) * Wl;
    #pragma unroll
    for (int ci = threadIdx.y; ci < 32; ci += 8)
        s[ci][threadIdx.x] = base[(size_t)ci * Hl * Wl + x0 + threadIdx.x];
    __syncthreads();
    __half* ob = outp + (((size_t)bh * Hl + y) * Wl) * 32;
    #pragma unroll
    for (int xi = threadIdx.y; xi < 32; xi += 8)
        ob[(size_t)(x0 + xi) * 32 + threadIdx.x] = __float2half(s[threadIdx.x][xi]);
}

// ---------------- main fused kernel ------------------------------------------
#define SM_UT   0          // u_t [c*34 + r], 192*34 = 6528  (reused as ht)
#define SM_OFFS 6528       // offs [32*144] = 4608 (phi aliases start here)
#define SM_PHI  6528
#define SM_WTS  11136      // wts [32*72] = 2304 (aliased as LN partials first)
#define SM_AX   13440
#define SM_AY   13472
#define SM_IDX  13504
#define SM_MU   13536
#define SM_RS   13568
#define SM_TOTF 13600

__global__ void __launch_bounds__(256, 3)
main_kernel(const int*   __restrict__ top_indices,
            const float* __restrict__ qc,
            const float* __restrict__ ln_g,
            const float* __restrict__ ln_b,
            const float* __restrict__ w_delta_b,
            const float* __restrict__ w_a_b,
            const float* __restrict__ w_o_b,
            const float* __restrict__ e_def,
            float* __restrict__ out)
{
    extern __shared__ float sm[];
    float* u_t  = sm + SM_UT;     // [c*34 + r]
    float* offs = sm + SM_OFFS;
    float* phi  = sm + SM_PHI;
    float* wts  = sm + SM_WTS;
    float* ax_s = sm + SM_AX;
    float* ay_s = sm + SM_AY;
    int*   idx_s = (int*)(sm + SM_IDX);
    float* mu_s = sm + SM_MU;
    float* rs_s = sm + SM_RS;

    int tid  = threadIdx.x;
    int lane = tid & 31;
    int wid  = tid >> 5;
    int bk   = blockIdx.x;         // b*256 + k
    int b    = bk >> 8;

    // ---- anchors ----
    if (tid < 32) {
        int id = top_indices[(size_t)bk * RR + tid];
        idx_s[tid] = id;
        ax_s[tid] = (float)(id & 31) * 32.f + 16.f;
        ay_s[tid] = (float)(id >> 5) * 32.f + 16.f;
    }
    __syncthreads();

    // ---- fourier PE ----
    {
        int r = tid >> 3, j = tid & 7;
        float qx = qc[(size_t)bk*2 + 0];
        float qy = qc[(size_t)bk*2 + 1];
        float dxn  = (ax_s[r] - qx) * (1.f/1024.f);
        float dyn_ = (ay_s[r] - qy) * (1.f/1024.f);
        float f = (float)(1 << j);
        float xa = (dxn  * f) * 6.283185307179586f;
        float ya = (dyn_ * f) * 6.283185307179586f;
        float sx, cx, sy, cy;
        sincosf(xa, &sx, &cx);
        sincosf(ya, &sy, &cy);
        phi[r*32 + j]      = sx;
        phi[r*32 + 8 + j]  = cx;
        phi[r*32 + 16 + j] = sy;
        phi[r*32 + 24 + j] = cy;
    }
    __syncthreads();

    // ---- phase A: gelu(hpre + gpre[idx] + phi @ Wphi^T) -> u_t (pre-LN) ----
    if (tid < 192) {
        float wphi[32];
        #pragma unroll
        for (int i = 0; i < 32; ++i)
            wphi[i] = d_wuT[(size_t)(384 + i)*192 + tid];   // coalesced
        float hbase = d_hpre[(size_t)bk*192 + tid];
        for (int rb = 0; rb < 32; rb += 4) {
            float gv[4];
            #pragma unroll
            for (int q = 0; q < 4; ++q)
                gv[q] = d_gpre[((size_t)(b*NTOK + idx_s[rb + q])) * 192 + tid];
            #pragma unroll
            for (int q = 0; q < 4; ++q) {
                int r = rb + q;
                float acc = hbase + gv[q];
                const float4* ph = (const float4*)(phi + r*32);
                #pragma unroll
                for (int c4 = 0; c4 < 8; ++c4) {
                    float4 pv = ph[c4];
                    acc += pv.x*wphi[4*c4] + pv.y*wphi[4*c4+1]
                         + pv.z*wphi[4*c4+2] + pv.w*wphi[4*c4+3];
                }
                float gel = 0.5f * acc * (1.f + erff(acc * 0.70710678118654752f));
                u_t[tid*34 + r] = gel;
            }
        }
    }
    __syncthreads();

    // ---- LN stats: warp wid sums c-segment [wid*24, wid*24+24), lane = row --
    {
        float s1 = 0.f, s2 = 0.f;
        int c0 = wid * 24;
        for (int cc = c0; cc < c0 + 24; ++cc) {
            float v = u_t[cc*34 + lane];
            s1 += v; s2 += v*v;
        }
        wts[wid*32 + lane]       = s1;
        wts[256 + wid*32 + lane] = s2;
    }
    __syncthreads();
    if (tid < 32) {
        float s1 = 0.f, s2 = 0.f;
        #pragma unroll
        for (int w = 0; w < 8; ++w) {
            s1 += wts[w*32 + tid];
            s2 += wts[256 + w*32 + tid];
        }
        float mu  = s1 * (1.f/192.f);
        float var = s2 * (1.f/192.f) - mu*mu;
        mu_s[tid] = mu;
        rs_s[tid] = rsqrtf(var + 1e-5f);
    }
    __syncthreads();

    // ---- LN apply: column owner ----
    if (tid < 192) {
        float gg = ln_g[tid], bb = ln_b[tid];
        #pragma unroll 4
        for (int r = 0; r < 32; ++r) {
            float v = u_t[tid*34 + r];
            u_t[tid*34 + r] = (v - mu_s[r]) * rs_s[r] * gg + bb;
        }
    }
    __syncthreads();

    // ---- phase B: [32x192] @ [192x216]; rg in low 2 bits -> w-LDG dedup -----
    if (tid < 216) {
        int rg = tid & 3;
        int cg = tid >> 2;            // 0..53
        int r0 = rg * 8;
        unsigned long long acc[4][4];
        #pragma unroll
        for (int j = 0; j < 4; ++j)
            #pragma unroll
            for (int p = 0; p < 4; ++p) acc[j][p] = 0ull;
        const float2* wb = d_wdT2 + cg;
        for (int c2 = 0; c2 < 96; ++c2) {
            unsigned long long u0[4], u1[4];
            const float* ub0 = u_t + (2*c2)*34 + r0;
            const float* ub1 = ub0 + 34;
            #pragma unroll
            for (int p = 0; p < 4; ++p) {
                u0[p] = *(const unsigned long long*)(ub0 + 2*p);
                u1[p] = *(const unsigned long long*)(ub1 + 2*p);
            }
            #pragma unroll
            for (int j = 0; j < 4; ++j) {
                float2 wv = wb[c2*216 + 54*j];
                unsigned long long w0 = pack2(wv.x, wv.x);
                unsigned long long w1 = pack2(wv.y, wv.y);
                #pragma unroll
                for (int p = 0; p < 4; ++p) {
                    fma2(acc[j][p], u0[p], w0);
                    fma2(acc[j][p], u1[p], w1);
                }
            }
        }
        #pragma unroll
        for (int j = 0; j < 4; ++j) {
            int o = cg + 54*j;
            if (o < 144) {
                float bb = w_delta_b[o];
                int l = (o >> 3) % 3;
                float sg = (l == 0) ? 4.f : ((l == 1) ? 2.f : 1.f);
                #pragma unroll
                for (int p = 0; p < 4; ++p) {
                    float2 v = unpack2(acc[j][p]);
                    offs[(r0 + 2*p    )*144 + o] = tanhf(v.x + bb) * sg;
                    offs[(r0 + 2*p + 1)*144 + o] = tanhf(v.y + bb) * sg;
                }
            } else {
                int oa = o - 144;
                float bb = w_a_b[oa];
                #pragma unroll
                for (int p = 0; p < 4; ++p) {
                    float2 v = unpack2(acc[j][p]);
                    wts[(r0 + 2*p    )*72 + oa] = v.x + bb;
                    wts[(r0 + 2*p + 1)*72 + oa] = v.y + bb;
                }
            }
        }
    }
    __syncthreads();

    // ---- softmax over L*M=12 per (row, head) --------------------------------
    if (tid < 192) {
        int r = tid & 31, hh = tid >> 5;
        float* wp = wts + r*72 + hh*12;
        float mx = wp[0];
        #pragma unroll
        for (int t = 1; t < 12; ++t) mx = fmaxf(mx, wp[t]);
        float s = 0.f;
        #pragma unroll
        for (int t = 0; t < 12; ++t) { float e = __expf(wp[t] - mx); wp[t] = e; s += e; }
        float inv = 1.f / s;
        #pragma unroll
        for (int t = 0; t < 12; ++t) wp[t] *= inv;
    }
    __syncthreads();

    // ---- phase C: bilinear; 4-lane units, 8 fp16 channels per lane ----------
    {
        float* ht = u_t;                  // alias; u values dead now
        int qlane = lane >> 2;            // unit within warp
        int c8i   = lane & 3;             // channel-quarter (8 ch)
        #pragma unroll
        for (int pass = 0; pass < 3; ++pass) {
            int uu = pass*64 + wid*8 + qlane;
            int r = uu & 31, hh = uu >> 5;
            float axr = ax_s[r], ayr = ay_s[r];
            const float* op = offs + r*144 + hh*24;
            const float* wp = wts + r*72 + hh*12;
            float acc[8];
            #pragma unroll
            for (int k = 0; k < 8; ++k) acc[k] = 0.f;
            #pragma unroll
            for (int l = 0; l < 3; ++l) {
                int Hl = 128 >> l, Wl = 128 >> l;
                const uint4* ft4;
                float scl;
                if (l == 0) { ft4 = (const uint4*)d_ft0 + ((size_t)(b*NH+hh)*128*128)*4 + c8i; scl = 0.125f; }
                else if (l == 1) { ft4 = (const uint4*)d_ft1 + ((size_t)(b*NH+hh)*64*64)*4 + c8i; scl = 0.0625f; }
                else { ft4 = (const uint4*)d_ft2 + ((size_t)(b*NH+hh)*32*32)*4 + c8i; scl = 0.03125f; }
                float afx = axr*scl, afy = ayr*scl;
                #pragma unroll
                for (int m = 0; m < 4; ++m) {
                    float px = afx + op[l*8 + 2*m];
                    float py = afy + op[l*8 + 2*m + 1];
                    float wgt = wp[l*4 + m];
                    float x0f = floorf(px), y0f = floorf(py);
                    float fx = px - x0f, fy = py - y0f;
                    int x0 = (int)x0f, y0 = (int)y0f;
                    float wx0 = 1.f - fx, wy0 = 1.f - fy;
                    float cw[4] = { wgt*wx0*wy0, wgt*fx*wy0, wgt*wx0*fy, wgt*fx*fy };
                    #pragma unroll
                    for (int corner = 0; corner < 4; ++corner) {
                        int xx = x0 + (corner & 1);
                        int yy = y0 + (corner >> 1);
                        if (((unsigned)xx < (unsigned)Wl) && ((unsigned)yy < (unsigned)Hl)) {
                            uint4 raw = ft4[((size_t)yy*Wl + xx)*4];
                            const __half2* hp = (const __half2*)&raw;
                            float w = cw[corner];
                            #pragma unroll
                            for (int k = 0; k < 4; ++k) {
                                float2 f2 = __half22float2(hp[k]);
                                acc[2*k]   += w * f2.x;
                                acc[2*k+1] += w * f2.y;
                            }
                        }
                    }
                }
            }
            int cbase = hh*32 + c8i*8;
            #pragma unroll
            for (int k = 0; k < 8; ++k)
                ht[(cbase + k)*34 + r] = acc[k];
        }
    }
    __syncthreads();

    // ---- phase D: [32x192] @ [192x192]; rg in low 2 bits -> w-LDG dedup -----
    if (tid < 192) {
        float* ht = u_t;
        int rg = tid & 3;
        int cg = tid >> 2;            // 0..47
        int r0 = rg * 8;
        unsigned long long acc[4][4];
        #pragma unroll
        for (int j = 0; j < 4; ++j)
            #pragma unroll
            for (int p = 0; p < 4; ++p) acc[j][p] = 0ull;
        const float2* wb = d_woT2 + cg;
        for (int c2 = 0; c2 < 96; ++c2) {
            unsigned long long u0[4], u1[4];
            const float* ub0 = ht + (2*c2)*34 + r0;
            const float* ub1 = ub0 + 34;
            #pragma unroll
            for (int p = 0; p < 4; ++p) {
                u0[p] = *(const unsigned long long*)(ub0 + 2*p);
                u1[p] = *(const unsigned long long*)(ub1 + 2*p);
            }
            #pragma unroll
            for (int j = 0; j < 4; ++j) {
                float2 wv = wb[c2*192 + 48*j];
                unsigned long long w0 = pack2(wv.x, wv.x);
                unsigned long long w1 = pack2(wv.y, wv.y);
                #pragma unroll
                for (int p = 0; p < 4; ++p) {
                    fma2(acc[j][p], u0[p], w0);
                    fma2(acc[j][p], u1[p], w1);
                }
            }
        }
        #pragma unroll
        for (int j = 0; j < 4; ++j) {
            int d = cg + 48*j;
            float bb = w_o_b[d] + e_def[d];
            #pragma unroll
            for (int p = 0; p < 4; ++p) {
                float2 v = unpack2(acc[j][p]);
                out[((size_t)bk*RR + r0 + 2*p    )*192 + d] = v.x + bb;
                out[((size_t)bk*RR + r0 + 2*p + 1)*192 + d] = v.y + bb;
            }
        }
    }
}

// ---------------- launch ------------------------------------------------------
extern "C" void kernel_launch(void* const* d_in, const int* in_sizes, int n_in,
                              void* d_out, int out_size)
{
    const float* h     = (const float*)d_in[0];
    const int*   top   = (const int*)  d_in[1];
    const float* qc    = (const float*)d_in[2];
    const float* g     = (const float*)d_in[3];
    const float* L2p   = (const float*)d_in[4];
    const float* L3p   = (const float*)d_in[5];
    const float* L4p   = (const float*)d_in[6];
    const float* w_u_w = (const float*)d_in[7];
    const float* w_u_b = (const float*)d_in[8];
    const float* ln_g  = (const float*)d_in[9];
    const float* ln_b  = (const float*)d_in[10];
    const float* w_d_w = (const float*)d_in[11];
    const float* w_d_b = (const float*)d_in[12];
    const float* w_a_w = (const float*)d_in[13];
    const float* w_a_b = (const float*)d_in[14];
    const float* w_o_w = (const float*)d_in[15];
    const float* w_o_b = (const float*)d_in[16];
    const float* e_def = (const float*)d_in[17];
    float* out = (float*)d_out;

    // launch 0: weight prep
    wprep_kernel<<<64, 256>>>(w_u_w, w_d_w, w_a_w, w_o_w);
    // launch 1: merged precompute (g then h)
    pre_merged_kernel<<<80, 192>>>(g, h, w_u_b);
    // launch 2: merged feature transpose
    transpose_merged_kernel<<<8064, dim3(32, 8)>>>(L2p, L3p, L4p);
    // launch 3: main fused kernel (profiled slot)
    const int smem_bytes = SM_TOTF * 4;
    cudaFuncSetAttribute(main_kernel, cudaFuncAttributeMaxDynamicSharedMemorySize, smem_bytes);
    main_kernel<<<BB*KK, 256, smem_bytes>>>(top, qc, ln_g, ln_b,
                                            w_d_b, w_a_b, w_o_b, e_def, out);
}

// round 7
// speedup vs baseline: 1.8972x; 1.1795x over previous
#include <cuda_runtime.h>
#include <cuda_fp16.h>
#include <math.h>

#define BB 2
#define KK 256
#define RR 32
#define DD 192
#define NH 6
#define DH 32
#define NTOK 1024   // 32*32 L4 tokens per batch

// ---------------- scratch (device globals; no allocs allowed) ----------------
__device__ __half d_ft0[(size_t)BB*NH*128*128*32];  // level0 channels-last fp16
__device__ __half d_ft1[(size_t)BB*NH*64*64*32];    // level1
__device__ __half d_ft2[(size_t)BB*NH*32*32*32];    // level2
__device__ float  d_gpre[(size_t)BB*NTOK*DD];       // g @ W_u[:,192:384]
__device__ float  d_hpre[(size_t)BB*KK*DD];         // h @ W_u[:,0:192] + b_u
__device__ float  d_wuT [(size_t)416*192];          // W_u^T  [c][d]
__device__ float2 d_wdT2[(size_t)96*216];           // delta+a weights, (c/2, o){c%2}
__device__ float2 d_woT2[(size_t)96*192];           // W_o, (c/2, o){c%2}

// ---------------- f32x2 packed-FMA helpers (Blackwell) ------------------------
__device__ __forceinline__ unsigned long long pack2(float x, float y) {
    unsigned long long r;
    asm("mov.b64 %0, {%1, %2};" : "=l"(r) : "f"(x), "f"(y));
    return r;
}
__device__ __forceinline__ void fma2(unsigned long long& d, unsigned long long a,
                                     unsigned long long b) {
    asm("fma.rn.f32x2 %0, %1, %2, %0;" : "+l"(d) : "l"(a), "l"(b));
}
__device__ __forceinline__ float2 unpack2(unsigned long long v) {
    float2 r;
    asm("mov.b64 {%0, %1}, %2;" : "=f"(r.x), "=f"(r.y) : "l"(v));
    return r;
}
// fast tanh via MUFU EX2 (abs err ~1e-6; exact saturation at +-inf)
__device__ __forceinline__ float ftanh(float x) {
    float e = __expf(2.f * x);
    return 1.f - __fdividef(2.f, e + 1.f);
}

// ---------------- weight prep: transposed / interleaved layouts --------------
__global__ void wprep_kernel(const float* __restrict__ wu,
                             const float* __restrict__ wd,
                             const float* __restrict__ wa,
                             const float* __restrict__ wo)
{
    int i0 = blockIdx.x * blockDim.x + threadIdx.x;
    int stride = gridDim.x * blockDim.x;
    for (int i = i0; i < 416*192; i += stride) {
        int c = i / 192, d = i - c*192;
        d_wuT[i] = wu[(size_t)d*416 + c];
    }
    float* wd2 = (float*)d_wdT2;
    for (int i = i0; i < 96*216*2; i += stride) {
        int c2 = i / 432; int rem = i - c2*432;
        int o = rem >> 1; int ci = rem & 1;
        int c = 2*c2 + ci;
        wd2[i] = (o < 144) ? wd[(size_t)o*192 + c] : wa[(size_t)(o-144)*192 + c];
    }
    float* wo2 = (float*)d_woT2;
    for (int i = i0; i < 96*192*2; i += stride) {
        int c2 = i / 384; int rem = i - c2*384;
        int o = rem >> 1; int ci = rem & 1;
        int c = 2*c2 + ci;
        wo2[i] = wo[(size_t)o*192 + c];
    }
}

// ---------------- merged precompute: X @ WuT slice ---------------------------
__global__ void __launch_bounds__(192)
pre_merged_kernel(const float* __restrict__ g, const float* __restrict__ h,
                  const float* __restrict__ bias)
{
    __shared__ float xs[32*192];      // row-major [r][c]
    int bx = blockIdx.x;
    const float* X; float* outp; int colOff, r0;
    bool useBias;
    if (bx < 64) { X = g; outp = d_gpre; colOff = 192; r0 = bx*32; useBias = false; }
    else         { X = h; outp = d_hpre; colOff = 0;   r0 = (bx-64)*32; useBias = true; }
    int tid = threadIdx.x;
    for (int i = tid; i < 32*192; i += 192)
        xs[i] = X[(size_t)r0*192 + i];
    __syncthreads();
    int rg = tid & 3;                 // adjacent lanes share cg -> LDG dedup
    int cg = tid >> 2;                // 0..47
    int rr0 = rg * 8;
    float acc[4][8];
    #pragma unroll
    for (int j = 0; j < 4; ++j)
        #pragma unroll
        for (int q = 0; q < 8; ++q) acc[j][q] = 0.f;
    const float* wbase = d_wuT + (size_t)colOff*192 + cg;
    for (int c = 0; c < 192; ++c) {
        float wv[4];
        #pragma unroll
        for (int j = 0; j < 4; ++j) wv[j] = wbase[c*192 + 48*j];
        #pragma unroll
        for (int q = 0; q < 8; ++q) {
            float xv = xs[(rr0 + q)*192 + c];
            #pragma unroll
            for (int j = 0; j < 4; ++j) acc[j][q] += xv * wv[j];
        }
    }
    #pragma unroll
    for (int j = 0; j < 4; ++j) {
        int col = cg + 48*j;
        float bb = useBias ? bias[col] : 0.f;
        #pragma unroll
        for (int q = 0; q < 8; ++q)
            outp[(size_t)(r0 + rr0 + q)*192 + col] = acc[j][q] + bb;
    }
}

// ---------------- merged feature transpose -----------------------------------
__global__ void transpose_merged_kernel(const float* __restrict__ L2p,
                                        const float* __restrict__ L3p,
                                        const float* __restrict__ L4p)
{
    __shared__ float s[32][33];
    int bid = blockIdx.x;
    const float* in; __half* outp; int Hl, Wl, xb, y, bh;
    if (bid < 6144) {
        Hl = Wl = 128; in = L2p; outp = d_ft0;
        int t = bid; xb = t & 3; t >>= 2; y = t & 127; bh = t >> 7;
    } else if (bid < 7680) {
        Hl = Wl = 64; in = L3p; outp = d_ft1;
        int t = bid - 6144; xb = t & 1; t >>= 1; y = t & 63; bh = t >> 6;
    } else {
        Hl = Wl = 32; in = L4p; outp = d_ft2;
        int t = bid - 7680; xb = 0; y = t & 31; bh = t >> 5;
    }
    int x0 = xb * 32;
    int b = bh / NH, hh = bh % NH;
    const float* base = in + (((size_t)b*DD + hh*DH) * Hl + y) * Wl;
    #pragma unroll
    for (int ci = threadIdx.y; ci < 32; ci += 8)
        s[ci][threadIdx.x] = base[(size_t)ci * Hl * Wl + x0 + threadIdx.x];
    __syncthreads();
    __half* ob = outp + (((size_t)bh * Hl + y) * Wl) * 32;
    #pragma unroll
    for (int xi = threadIdx.y; xi < 32; xi += 8)
        ob[(size_t)(x0 + xi) * 32 + threadIdx.x] = __float2half(s[threadIdx.x][xi]);
}

// ---------------- main fused kernel ------------------------------------------
#define SM_UT   0          // u_t [c*34 + r], 192*34 = 6528  (reused as ht)
#define SM_OFFS 6528       // offs [32*144] = 4608 (phi aliases start here)
#define SM_PHI  6528
#define SM_WTS  11136      // wts [32*72] = 2304 (aliased as LN partials first)
#define SM_AX   13440
#define SM_AY   13472
#define SM_IDX  13504
#define SM_MU   13536
#define SM_RS   13568
#define SM_TOTF 13600

__global__ void __launch_bounds__(256, 4)
main_kernel(const int*   __restrict__ top_indices,
            const float* __restrict__ qc,
            const float* __restrict__ ln_g,
            const float* __restrict__ ln_b,
            const float* __restrict__ w_delta_b,
            const float* __restrict__ w_a_b,
            const float* __restrict__ w_o_b,
            const float* __restrict__ e_def,
            float* __restrict__ out)
{
    extern __shared__ float sm[];
    float* u_t  = sm + SM_UT;     // [c*34 + r]
    float* offs = sm + SM_OFFS;
    float* phi  = sm + SM_PHI;
    float* wts  = sm + SM_WTS;
    float* ax_s = sm + SM_AX;
    float* ay_s = sm + SM_AY;
    int*   idx_s = (int*)(sm + SM_IDX);
    float* mu_s = sm + SM_MU;
    float* rs_s = sm + SM_RS;

    int tid  = threadIdx.x;
    int lane = tid & 31;
    int wid  = tid >> 5;
    int bk   = blockIdx.x;         // b*256 + k
    int b    = bk >> 8;

    // ---- anchors ----
    if (tid < 32) {
        int id = top_indices[(size_t)bk * RR + tid];
        idx_s[tid] = id;
        ax_s[tid] = (float)(id & 31) * 32.f + 16.f;
        ay_s[tid] = (float)(id >> 5) * 32.f + 16.f;
    }
    __syncthreads();

    // ---- fourier PE (fast sincos; |arg| <= ~805 rad, error << budget) ----
    {
        int r = tid >> 3, j = tid & 7;
        float qx = qc[(size_t)bk*2 + 0];
        float qy = qc[(size_t)bk*2 + 1];
        float dxn  = (ax_s[r] - qx) * (1.f/1024.f);
        float dyn_ = (ay_s[r] - qy) * (1.f/1024.f);
        float f = (float)(1 << j);
        float xa = (dxn  * f) * 6.283185307179586f;
        float ya = (dyn_ * f) * 6.283185307179586f;
        float sx, cx, sy, cy;
        __sincosf(xa, &sx, &cx);
        __sincosf(ya, &sy, &cy);
        phi[r*32 + j]      = sx;
        phi[r*32 + 8 + j]  = cx;
        phi[r*32 + 16 + j] = sy;
        phi[r*32 + 24 + j] = cy;
    }
    __syncthreads();

    // ---- phase A: gelu(hpre + gpre[idx] + phi @ Wphi^T), two 16-wide K-chunks
    if (tid < 192) {
        // chunk 0: partial dot into u_t (same-thread staging, no sync needed)
        {
            float w16[16];
            #pragma unroll
            for (int i = 0; i < 16; ++i)
                w16[i] = d_wuT[(size_t)(384 + i)*192 + tid];
            #pragma unroll 2
            for (int r = 0; r < 32; ++r) {
                const float4* ph = (const float4*)(phi + r*32);
                float acc = 0.f;
                #pragma unroll
                for (int c4 = 0; c4 < 4; ++c4) {
                    float4 pv = ph[c4];
                    acc += pv.x*w16[4*c4] + pv.y*w16[4*c4+1]
                         + pv.z*w16[4*c4+2] + pv.w*w16[4*c4+3];
                }
                u_t[tid*34 + r] = acc;
            }
        }
        // chunk 1: finish, add h/g, gelu
        {
            float w16[16];
            #pragma unroll
            for (int i = 0; i < 16; ++i)
                w16[i] = d_wuT[(size_t)(400 + i)*192 + tid];
            float hbase = d_hpre[(size_t)bk*192 + tid];
            for (int rb = 0; rb < 32; rb += 4) {
                float gv[4];
                #pragma unroll
                for (int q = 0; q < 4; ++q)
                    gv[q] = d_gpre[((size_t)(b*NTOK + idx_s[rb + q])) * 192 + tid];
                #pragma unroll
                for (int q = 0; q < 4; ++q) {
                    int r = rb + q;
                    float acc = u_t[tid*34 + r] + hbase + gv[q];
                    const float4* ph = (const float4*)(phi + r*32 + 16);
                    #pragma unroll
                    for (int c4 = 0; c4 < 4; ++c4) {
                        float4 pv = ph[c4];
                        acc += pv.x*w16[4*c4] + pv.y*w16[4*c4+1]
                             + pv.z*w16[4*c4+2] + pv.w*w16[4*c4+3];
                    }
                    float gel = 0.5f * acc * (1.f + erff(acc * 0.70710678118654752f));
                    u_t[tid*34 + r] = gel;
                }
            }
        }
    }
    __syncthreads();

    // ---- LN stats: warp wid sums c-segment [wid*24, wid*24+24), lane = row --
    {
        float s1 = 0.f, s2 = 0.f;
        int c0 = wid * 24;
        for (int cc = c0; cc < c0 + 24; ++cc) {
            float v = u_t[cc*34 + lane];
            s1 += v; s2 += v*v;
        }
        wts[wid*32 + lane]       = s1;
        wts[256 + wid*32 + lane] = s2;
    }
    __syncthreads();
    if (tid < 32) {
        float s1 = 0.f, s2 = 0.f;
        #pragma unroll
        for (int w = 0; w < 8; ++w) {
            s1 += wts[w*32 + tid];
            s2 += wts[256 + w*32 + tid];
        }
        float mu  = s1 * (1.f/192.f);
        float var = s2 * (1.f/192.f) - mu*mu;
        mu_s[tid] = mu;
        rs_s[tid] = rsqrtf(var + 1e-5f);
    }
    __syncthreads();

    // ---- LN apply: column owner ----
    if (tid < 192) {
        float gg = ln_g[tid], bb = ln_b[tid];
        #pragma unroll 4
        for (int r = 0; r < 32; ++r) {
            float v = u_t[tid*34 + r];
            u_t[tid*34 + r] = (v - mu_s[r]) * rs_s[r] * gg + bb;
        }
    }
    __syncthreads();

    // ---- phase B: [32x192] @ [192x216]; rg in low 2 bits -> w-LDG dedup -----
    if (tid < 216) {
        int rg = tid & 3;
        int cg = tid >> 2;            // 0..53
        int r0 = rg * 8;
        unsigned long long acc[4][4];
        #pragma unroll
        for (int j = 0; j < 4; ++j)
            #pragma unroll
            for (int p = 0; p < 4; ++p) acc[j][p] = 0ull;
        const float2* wb = d_wdT2 + cg;
        for (int c2 = 0; c2 < 96; ++c2) {
            unsigned long long u0[4], u1[4];
            const float* ub0 = u_t + (2*c2)*34 + r0;
            const float* ub1 = ub0 + 34;
            #pragma unroll
            for (int p = 0; p < 4; ++p) {
                u0[p] = *(const unsigned long long*)(ub0 + 2*p);
                u1[p] = *(const unsigned long long*)(ub1 + 2*p);
            }
            #pragma unroll
            for (int j = 0; j < 4; ++j) {
                float2 wv = wb[c2*216 + 54*j];
                unsigned long long w0 = pack2(wv.x, wv.x);
                unsigned long long w1 = pack2(wv.y, wv.y);
                #pragma unroll
                for (int p = 0; p < 4; ++p) {
                    fma2(acc[j][p], u0[p], w0);
                    fma2(acc[j][p], u1[p], w1);
                }
            }
        }
        #pragma unroll
        for (int j = 0; j < 4; ++j) {
            int o = cg + 54*j;
            if (o < 144) {
                float bb = w_delta_b[o];
                int l = (o >> 3) % 3;
                float sg = (l == 0) ? 4.f : ((l == 1) ? 2.f : 1.f);
                #pragma unroll
                for (int p = 0; p < 4; ++p) {
                    float2 v = unpack2(acc[j][p]);
                    offs[(r0 + 2*p    )*144 + o] = ftanh(v.x + bb) * sg;
                    offs[(r0 + 2*p + 1)*144 + o] = ftanh(v.y + bb) * sg;
                }
            } else {
                int oa = o - 144;
                float bb = w_a_b[oa];
                #pragma unroll
                for (int p = 0; p < 4; ++p) {
                    float2 v = unpack2(acc[j][p]);
                    wts[(r0 + 2*p    )*72 + oa] = v.x + bb;
                    wts[(r0 + 2*p + 1)*72 + oa] = v.y + bb;
                }
            }
        }
    }
    __syncthreads();

    // ---- softmax over L*M=12 per (row, head) --------------------------------
    if (tid < 192) {
        int r = tid & 31, hh = tid >> 5;
        float* wp = wts + r*72 + hh*12;
        float mx = wp[0];
        #pragma unroll
        for (int t = 1; t < 12; ++t) mx = fmaxf(mx, wp[t]);
        float s = 0.f;
        #pragma unroll
        for (int t = 0; t < 12; ++t) { float e = __expf(wp[t] - mx); wp[t] = e; s += e; }
        float inv = 1.f / s;
        #pragma unroll
        for (int t = 0; t < 12; ++t) wp[t] *= inv;
    }
    __syncthreads();

    // ---- phase C: bilinear, branchless (clamped addr, zeroed weight) --------
    {
        float* ht = u_t;                  // alias; u values dead now
        int qlane = lane >> 2;            // unit within warp
        int c8i   = lane & 3;             // channel-quarter (8 ch)
        #pragma unroll
        for (int pass = 0; pass < 3; ++pass) {
            int uu = pass*64 + wid*8 + qlane;
            int r = uu & 31, hh = uu >> 5;
            float axr = ax_s[r], ayr = ay_s[r];
            const float* op = offs + r*144 + hh*24;
            const float* wp = wts + r*72 + hh*12;
            float acc[8];
            #pragma unroll
            for (int k = 0; k < 8; ++k) acc[k] = 0.f;
            #pragma unroll
            for (int l = 0; l < 3; ++l) {
                int Hl = 128 >> l, Wl = 128 >> l;
                const uint4* ft4;
                float scl;
                if (l == 0) { ft4 = (const uint4*)d_ft0 + ((size_t)(b*NH+hh)*128*128)*4 + c8i; scl = 0.125f; }
                else if (l == 1) { ft4 = (const uint4*)d_ft1 + ((size_t)(b*NH+hh)*64*64)*4 + c8i; scl = 0.0625f; }
                else { ft4 = (const uint4*)d_ft2 + ((size_t)(b*NH+hh)*32*32)*4 + c8i; scl = 0.03125f; }
                float afx = axr*scl, afy = ayr*scl;
                #pragma unroll
                for (int m = 0; m < 4; ++m) {
                    float px = afx + op[l*8 + 2*m];
                    float py = afy + op[l*8 + 2*m + 1];
                    float wgt = wp[l*4 + m];
                    float x0f = floorf(px), y0f = floorf(py);
                    float fx = px - x0f, fy = py - y0f;
                    int x0 = (int)x0f, y0 = (int)y0f;
                    float wx0 = 1.f - fx, wy0 = 1.f - fy;
                    float cw[4] = { wgt*wx0*wy0, wgt*fx*wy0, wgt*wx0*fy, wgt*fx*fy };
                    #pragma unroll
                    for (int corner = 0; corner < 4; ++corner) {
                        int xx = x0 + (corner & 1);
                        int yy = y0 + (corner >> 1);
                        bool valid = ((unsigned)xx < (unsigned)Wl) && ((unsigned)yy < (unsigned)Hl);
                        int xc = min(max(xx, 0), Wl - 1);
                        int yc = min(max(yy, 0), Hl - 1);
                        float w = valid ? cw[corner] : 0.f;
                        uint4 raw = ft4[((size_t)yc*Wl + xc)*4];   // unconditional
                        const __half2* hp = (const __half2*)&raw;
                        #pragma unroll
                        for (int k = 0; k < 4; ++k) {
                            float2 f2 = __half22float2(hp[k]);
                            acc[2*k]   += w * f2.x;
                            acc[2*k+1] += w * f2.y;
                        }
                    }
                }
            }
            int cbase = hh*32 + c8i*8;
            #pragma unroll
            for (int k = 0; k < 8; ++k)
                ht[(cbase + k)*34 + r] = acc[k];
        }
    }
    __syncthreads();

    // ---- phase D: [32x192] @ [192x192]; rg in low 2 bits -> w-LDG dedup -----
    if (tid < 192) {
        float* ht = u_t;
        int rg = tid & 3;
        int cg = tid >> 2;            // 0..47
        int r0 = rg * 8;
        unsigned long long acc[4][4];
        #pragma unroll
        for (int j = 0; j < 4; ++j)
            #pragma unroll
            for (int p = 0; p < 4; ++p) acc[j][p] = 0ull;
        const float2* wb = d_woT2 + cg;
        for (int c2 = 0; c2 < 96; ++c2) {
            unsigned long long u0[4], u1[4];
            const float* ub0 = ht + (2*c2)*34 + r0;
            const float* ub1 = ub0 + 34;
            #pragma unroll
            for (int p = 0; p < 4; ++p) {
                u0[p] = *(const unsigned long long*)(ub0 + 2*p);
                u1[p] = *(const unsigned long long*)(ub1 + 2*p);
            }
            #pragma unroll
            for (int j = 0; j < 4; ++j) {
                float2 wv = wb[c2*192 + 48*j];
                unsigned long long w0 = pack2(wv.x, wv.x);
                unsigned long long w1 = pack2(wv.y, wv.y);
                #pragma unroll
                for (int p = 0; p < 4; ++p) {
                    fma2(acc[j][p], u0[p], w0);
                    fma2(acc[j][p], u1[p], w1);
                }
            }
        }
        #pragma unroll
        for (int j = 0; j < 4; ++j) {
            int d = cg + 48*j;
            float bb = w_o_b[d] + e_def[d];
            #pragma unroll
            for (int p = 0; p < 4; ++p) {
                float2 v = unpack2(acc[j][p]);
                out[((size_t)bk*RR + r0 + 2*p    )*192 + d] = v.x + bb;
                out[((size_t)bk*RR + r0 + 2*p + 1)*192 + d] = v.y + bb;
            }
        }
    }
}

// ---------------- launch ------------------------------------------------------
extern "C" void kernel_launch(void* const* d_in, const int* in_sizes, int n_in,
                              void* d_out, int out_size)
{
    const float* h     = (const float*)d_in[0];
    const int*   top   = (const int*)  d_in[1];
    const float* qc    = (const float*)d_in[2];
    const float* g     = (const float*)d_in[3];
    const float* L2p   = (const float*)d_in[4];
    const float* L3p   = (const float*)d_in[5];
    const float* L4p   = (const float*)d_in[6];
    const float* w_u_w = (const float*)d_in[7];
    const float* w_u_b = (const float*)d_in[8];
    const float* ln_g  = (const float*)d_in[9];
    const float* ln_b  = (const float*)d_in[10];
    const float* w_d_w = (const float*)d_in[11];
    const float* w_d_b = (const float*)d_in[12];
    const float* w_a_w = (const float*)d_in[13];
    const float* w_a_b = (const float*)d_in[14];
    const float* w_o_w = (const float*)d_in[15];
    const float* w_o_b = (const float*)d_in[16];
    const float* e_def = (const float*)d_in[17];
    float* out = (float*)d_out;

    // launch 0: weight prep
    wprep_kernel<<<64, 256>>>(w_u_w, w_d_w, w_a_w, w_o_w);
    // launch 1: merged precompute (g then h)
    pre_merged_kernel<<<80, 192>>>(g, h, w_u_b);
    // launch 2: merged feature transpose
    transpose_merged_kernel<<<8064, dim3(32, 8)>>>(L2p, L3p, L4p);
    // launch 3: main fused kernel (profiled slot)
    const int smem_bytes = SM_TOTF * 4;
    cudaFuncSetAttribute(main_kernel, cudaFuncAttributeMaxDynamicSharedMemorySize, smem_bytes);
    main_kernel<<<BB*KK, 256, smem_bytes>>>(top, qc, ln_g, ln_b,
                                            w_d_b, w_a_b, w_o_b, e_def, out);
}